// round 15
// baseline (speedup 1.0000x reference)
#include <cuda_runtime.h>
#include <cuda_fp16.h>
#include <cstdint>

#define BB 64
#define CC 64
#define DT6 (0.1f/6.0f)

// ---------------- scratch (device globals) ---------------------------------
static __device__ float  g_h1 [BB*128*128*64];   // fp32 NHWC
static __device__ __half g_h1h[BB*128*128*64];   // fp16 NHWC
static __device__ float  g_h2 [BB*64*64*64];     // fp32 NHWC
static __device__ __half g_h2h[BB*64*64*64];     // fp16 NHWC
static __device__ float  g_z  [BB*1024*64];      // fp32 NHWC (ODE state)
static __device__ __half g_zh [BB*1024*64];      // fp16 shadow of z
static __device__ __half g_u  [BB*1024*64];      // fp16: convA output
static __device__ __half g_ga [BB*1024*64];      // fp16: z+alpha*k
static __device__ float  g_ka [BB*1024*64];      // fp32 RK4 accumulator
static __device__ float2 g_scb[BB*CC];           // per-(b,c) GN scale/shift
static __device__ float  g_pool[BB*CC];
// packed B: [chunk][nt][gid][tig][4 b32]
static __device__ __half g_BpackH[36*2048];      // ODE weights
static __device__ __half g_B4[2*32*2048];        // conv4 weights
static __device__ float  g_Wcls[2*3*3*64];       // time-channel border sums

// ---------------- fp16 MMA -------------------------------------------------
__device__ __forceinline__ void mma_f16(float* c, uint32_t a0, uint32_t a1,
                                        uint32_t a2, uint32_t a3,
                                        uint32_t b0, uint32_t b1) {
    asm volatile(
        "mma.sync.aligned.m16n8k16.row.col.f32.f16.f16.f32 "
        "{%0,%1,%2,%3},{%4,%5,%6,%7},{%8,%9},{%0,%1,%2,%3};"
        : "+f"(c[0]), "+f"(c[1]), "+f"(c[2]), "+f"(c[3])
        : "r"(a0), "r"(a1), "r"(a2), "r"(a3), "r"(b0), "r"(b1));
}

// ---------------- weight prepack -------------------------------------------
__global__ __launch_bounds__(256)
void prep_w(const float* __restrict__ w1, const float* __restrict__ w2,
            const float* __restrict__ w4a, const float* __restrict__ w4b) {
    int i = blockIdx.x * 256 + threadIdx.x;
    if (i < 36 * 2048) {                    // ODE conv weights
        int e = i & 1, w4 = (i >> 1) & 3, tig = (i >> 3) & 3;
        int gid = (i >> 5) & 7, nt = (i >> 8) & 7;
        int c = i >> 11;                    // cv*18 + s9*2 + h
        int h = c & 1, s9 = (c >> 1) % 9, cv = c / 18;
        int dy = s9 / 3, dx = s9 % 3;
        int kk = w4 >> 1, bsel = w4 & 1;
        int k = kk * 16 + 2 * tig + bsel * 8 + e;
        int oc = nt * 8 + gid;
        const float* w = cv ? w2 : w1;
        int icg = h * 32 + k;
        g_BpackH[i] = __float2half(w[((oc * 65 + icg + 1) * 3 + dy) * 3 + dx]);
    }
    if (i < 2 * 32 * 2048) {                // conv4 weights
        int e = i & 1, w4 = (i >> 1) & 3, tig = (i >> 3) & 3;
        int gid = (i >> 5) & 7, nt = (i >> 8) & 7;
        int tix = (i >> 11) & 31;           // tap*2 + h
        int cv = i >> 16;
        int h = tix & 1, tap = tix >> 1;
        int ky = tap >> 2, kx = tap & 3;
        int kk = w4 >> 1, bsel = w4 & 1;
        int k = kk * 16 + 2 * tig + bsel * 8 + e;
        int oc = nt * 8 + gid;
        const float* w = cv ? w4b : w4a;
        int ic = h * 32 + k;
        g_B4[i] = __float2half(w[((oc * 64 + ic) * 4 + ky) * 4 + kx]);
    }
    if (i < 2 * 3 * 3 * 64) {               // time-channel border-class sums
        int oc = i & 63;
        int t2 = i >> 6;
        int xs = t2 % 3, ys = (t2 / 3) % 3, cv = t2 / 9;
        const float* w = cv ? w2 : w1;
        float s = 0.f;
        for (int dy = 0; dy < 3; dy++)
            for (int dx = 0; dx < 3; dx++) {
                bool okY = !((ys == 0 && dy == 0) || (ys == 2 && dy == 2));
                bool okX = !((xs == 0 && dx == 0) || (xs == 2 && dx == 2));
                if (okY && okX) s += w[(oc * 65 * 3 + dy) * 3 + dx];
            }
        g_Wcls[((cv * 3 + ys) * 3 + xs) * 64 + oc] = s;
    }
}

// ---------------- GN stats only: fp16 in -> per-(b,c) scale/shift -----------
__global__ __launch_bounds__(256)
void gn_stath(const __half* __restrict__ in, const float* __restrict__ gw,
              const float* __restrict__ gb, float2* __restrict__ scb) {
    __shared__ float4 shs[16][16], shq[16][16];
    int b = blockIdx.x, tid = threadIdx.x;
    int c4 = tid & 15, pg = tid >> 4;
    const uint2* ip = (const uint2*)in + (size_t)b * 16384;
    float4 s = {0, 0, 0, 0}, q = {0, 0, 0, 0};
#pragma unroll 4
    for (int i = 0; i < 64; i++) {
        uint2 r = ip[(pg * 64 + i) * 16 + c4];
        float2 fa = __half22float2(*(__half2*)&r.x);
        float2 fb = __half22float2(*(__half2*)&r.y);
        s.x += fa.x; s.y += fa.y; s.z += fb.x; s.w += fb.y;
        q.x += fa.x * fa.x; q.y += fa.y * fa.y;
        q.z += fb.x * fb.x; q.w += fb.y * fb.y;
    }
    shs[pg][c4] = s; shq[pg][c4] = q;
    __syncthreads();
    if (tid < 16) {
        float4 S = {0, 0, 0, 0}, Q = {0, 0, 0, 0};
#pragma unroll
        for (int g2 = 0; g2 < 16; g2++) {
            float4 a = shs[g2][tid], c = shq[g2][tid];
            S.x += a.x; S.y += a.y; S.z += a.z; S.w += a.w;
            Q.x += c.x; Q.y += c.y; Q.z += c.z; Q.w += c.w;
        }
        int c0 = tid * 4;
        float4 gw4 = ((const float4*)gw)[tid];
        float4 gb4 = ((const float4*)gb)[tid];
        float m, var, sc;
        m = S.x / 1024.f; var = Q.x / 1024.f - m * m; sc = gw4.x * rsqrtf(var + 1e-5f);
        scb[b * 64 + c0 + 0] = make_float2(sc, gb4.x - m * sc);
        m = S.y / 1024.f; var = Q.y / 1024.f - m * m; sc = gw4.y * rsqrtf(var + 1e-5f);
        scb[b * 64 + c0 + 1] = make_float2(sc, gb4.y - m * sc);
        m = S.z / 1024.f; var = Q.z / 1024.f - m * m; sc = gw4.z * rsqrtf(var + 1e-5f);
        scb[b * 64 + c0 + 2] = make_float2(sc, gb4.z - m * sc);
        m = S.w / 1024.f; var = Q.w / 1024.f - m * m; sc = gw4.w * rsqrtf(var + 1e-5f);
        scb[b * 64 + c0 + 3] = make_float2(sc, gb4.w - m * sc);
    }
}

// ---------------- HMMA ODE conv 3x3 pad1 (normalize-in-staging) -------------
// input = RAW pre-GN fp16; prologue applies GN (scale/shift from scb) + ReLU.
// MODE 0 (convA): outb = fp16(v)
// MODE 1 (k1):    ka = v;   outb = fp16(z + 0.05v)
// MODE 2 (k2):    ka += 2v; outb = fp16(z + 0.05v)
// MODE 3 (k3):    ka += 2v; outb = fp16(z + 0.10v)
// MODE 4 (k4):    z += DT6*(ka+v); zh = fp16(z')
template <int MODE>
__global__ __launch_bounds__(128)
void ode_conv_mma(const __half* __restrict__ g, const float2* __restrict__ scb,
                  const __half* __restrict__ wpk,
                  float t, const float* __restrict__ bias,
                  const float* __restrict__ wcls,
                  __half* __restrict__ outb, float* __restrict__ ka,
                  float* __restrict__ z, __half* __restrict__ zh) {
    __shared__ __half sA[192 * 72];
    __shared__ float ssc[64], ssf[64];
    int q = blockIdx.x, b = blockIdx.y;
    int tid = threadIdx.x;
    int w = tid >> 5, lane = tid & 31;
    int gid = lane >> 2, tig = lane & 3;
    int y = 4 * q + w;

    if (tid < 64) {
        float2 p = scb[b * 64 + tid];
        ssc[tid] = p.x; ssf[tid] = p.y;
    }
    __syncthreads();

    const __half* gb = g + (size_t)b * 65536;
#pragma unroll
    for (int j = 0; j < 12; j++) {
        int s = tid + 128 * j;
        int px = s >> 3, c8 = s & 7;
        int x = px & 31, yy = px >> 5;
        int yg = 4 * q - 1 + yy;
        uint4 v = make_uint4(0u, 0u, 0u, 0u);
        if (yg >= 0 && yg < 32) {
            uint4 r = *(const uint4*)(gb + ((size_t)yg * 32 + x) * 64 + c8 * 8);
            int c0 = c8 * 8;
            float2 f0 = __half22float2(*(__half2*)&r.x);
            float2 f1 = __half22float2(*(__half2*)&r.y);
            float2 f2 = __half22float2(*(__half2*)&r.z);
            float2 f3 = __half22float2(*(__half2*)&r.w);
            f0.x = fmaxf(fmaf(f0.x, ssc[c0+0], ssf[c0+0]), 0.f);
            f0.y = fmaxf(fmaf(f0.y, ssc[c0+1], ssf[c0+1]), 0.f);
            f1.x = fmaxf(fmaf(f1.x, ssc[c0+2], ssf[c0+2]), 0.f);
            f1.y = fmaxf(fmaf(f1.y, ssc[c0+3], ssf[c0+3]), 0.f);
            f2.x = fmaxf(fmaf(f2.x, ssc[c0+4], ssf[c0+4]), 0.f);
            f2.y = fmaxf(fmaf(f2.y, ssc[c0+5], ssf[c0+5]), 0.f);
            f3.x = fmaxf(fmaf(f3.x, ssc[c0+6], ssf[c0+6]), 0.f);
            f3.y = fmaxf(fmaf(f3.y, ssc[c0+7], ssf[c0+7]), 0.f);
            *(__half2*)&v.x = __floats2half2_rn(f0.x, f0.y);
            *(__half2*)&v.y = __floats2half2_rn(f1.x, f1.y);
            *(__half2*)&v.z = __floats2half2_rn(f2.x, f2.y);
            *(__half2*)&v.w = __floats2half2_rn(f3.x, f3.y);
        }
        *(uint4*)(&sA[px * 72 + c8 * 8]) = v;
    }
    __syncthreads();

    float acc[2][8][4];
#pragma unroll
    for (int mt = 0; mt < 2; mt++)
#pragma unroll
        for (int nt = 0; nt < 8; nt++)
#pragma unroll
            for (int j = 0; j < 4; j++) acc[mt][nt][j] = 0.f;

#pragma unroll
    for (int c = 0; c < 18; c++) {
        int s9 = c >> 1, h = c & 1;
        int dy = s9 / 3, dx = s9 % 3;
        int yyl = w + dy;

        int xA0 = gid + dx - 1;
        int xA1 = xA0 + 8, xA2 = xA0 + 16, xA3 = xA0 + 24;
        bool ok0 = (xA0 >= 0) && (xA0 < 32);
        bool ok1 = (xA1 >= 0) && (xA1 < 32);
        bool ok2 = (xA2 >= 0) && (xA2 < 32);
        bool ok3 = (xA3 >= 0) && (xA3 < 32);
        int r0 = (yyl * 32 + xA0) * 72 + h * 32;
        int r1 = (yyl * 32 + xA1) * 72 + h * 32;
        int r2 = (yyl * 32 + xA2) * 72 + h * 32;
        int r3 = (yyl * 32 + xA3) * 72 + h * 32;

        uint32_t A[2][2][4];
#pragma unroll
        for (int kk = 0; kk < 2; kk++) {
            int ic = kk * 16 + 2 * tig;
            A[kk][0][0] = ok0 ? *(const uint32_t*)(&sA[r0 + ic]) : 0u;
            A[kk][0][1] = ok1 ? *(const uint32_t*)(&sA[r1 + ic]) : 0u;
            A[kk][0][2] = ok0 ? *(const uint32_t*)(&sA[r0 + ic + 8]) : 0u;
            A[kk][0][3] = ok1 ? *(const uint32_t*)(&sA[r1 + ic + 8]) : 0u;
            A[kk][1][0] = ok2 ? *(const uint32_t*)(&sA[r2 + ic]) : 0u;
            A[kk][1][1] = ok3 ? *(const uint32_t*)(&sA[r3 + ic]) : 0u;
            A[kk][1][2] = ok2 ? *(const uint32_t*)(&sA[r2 + ic + 8]) : 0u;
            A[kk][1][3] = ok3 ? *(const uint32_t*)(&sA[r3 + ic + 8]) : 0u;
        }

        const uint4* wp4 = (const uint4*)(wpk + (size_t)c * 2048);
#pragma unroll
        for (int nt = 0; nt < 8; nt++) {
            uint4 wv = __ldg(wp4 + (nt * 8 + gid) * 4 + tig);
            mma_f16(acc[0][nt], A[0][0][0], A[0][0][1], A[0][0][2], A[0][0][3], wv.x, wv.y);
            mma_f16(acc[1][nt], A[0][1][0], A[0][1][1], A[0][1][2], A[0][1][3], wv.x, wv.y);
            mma_f16(acc[0][nt], A[1][0][0], A[1][0][1], A[1][0][2], A[1][0][3], wv.z, wv.w);
            mma_f16(acc[1][nt], A[1][1][0], A[1][1][1], A[1][1][2], A[1][1][3], wv.z, wv.w);
        }
    }

    int ys = (y == 0) ? 0 : ((y == 31) ? 2 : 1);
    const float* wcy = wcls + ys * 3 * 64;
#pragma unroll
    for (int mt = 0; mt < 2; mt++) {
#pragma unroll
        for (int rr = 0; rr < 2; rr++) {
            int x = mt * 16 + gid + rr * 8;
            int xs = (x == 0) ? 0 : ((x == 31) ? 2 : 1);
            const float* wcx = wcy + xs * 64;
            size_t base = ((size_t)b * 1024 + y * 32 + x) * 64;
#pragma unroll
            for (int nt = 0; nt < 8; nt++) {
                int oc = nt * 8 + 2 * tig;
                float2 v;
                v.x = acc[mt][nt][rr * 2 + 0] + __ldg(bias + oc) + t * __ldg(wcx + oc);
                v.y = acc[mt][nt][rr * 2 + 1] + __ldg(bias + oc + 1) + t * __ldg(wcx + oc + 1);
                if (MODE == 0) {
                    *(__half2*)(outb + base + oc) = __floats2half2_rn(v.x, v.y);
                } else if (MODE == 1) {
                    *(float2*)(ka + base + oc) = v;
                    float2 zz = *(const float2*)(z + base + oc);
                    *(__half2*)(outb + base + oc) =
                        __floats2half2_rn(zz.x + 0.05f * v.x, zz.y + 0.05f * v.y);
                } else if (MODE == 2 || MODE == 3) {
                    float2 a = *(const float2*)(ka + base + oc);
                    a.x += 2.f * v.x; a.y += 2.f * v.y;
                    *(float2*)(ka + base + oc) = a;
                    const float alpha = (MODE == 2) ? 0.05f : 0.1f;
                    float2 zz = *(const float2*)(z + base + oc);
                    *(__half2*)(outb + base + oc) =
                        __floats2half2_rn(zz.x + alpha * v.x, zz.y + alpha * v.y);
                } else {
                    float2 a = *(const float2*)(ka + base + oc);
                    float2 zz = *(const float2*)(z + base + oc);
                    zz.x += DT6 * (a.x + v.x);
                    zz.y += DT6 * (a.y + v.y);
                    *(float2*)(z + base + oc) = zz;
                    *(__half2*)(zh + base + oc) = __floats2half2_rn(zz.x, zz.y);
                }
            }
        }
    }
}

// ---------------- GN + ReLU + pool (head only, fp32 z) ----------------------
__global__ __launch_bounds__(256)
void gn_pool(const float* __restrict__ in, const float* __restrict__ gw,
             const float* __restrict__ gb, float* __restrict__ pool) {
    int b = blockIdx.x, qtr = blockIdx.y;
    int tid = threadIdx.x;
    int cl = tid & 3, c4 = qtr * 4 + cl, gg = tid >> 2;
    const float4* ip = (const float4*)in + (size_t)b * 16384;
    float4 s = {0, 0, 0, 0}, q2 = {0, 0, 0, 0};
#pragma unroll 4
    for (int i = 0; i < 16; i++) {
        float4 a = ip[(gg * 16 + i) * 16 + c4];
        s.x += a.x; s.y += a.y; s.z += a.z; s.w += a.w;
        q2.x += a.x * a.x; q2.y += a.y * a.y; q2.z += a.z * a.z; q2.w += a.w * a.w;
    }
    __shared__ float4 shs[64][4], shq[64][4];
    __shared__ float4 shsc[4], shsf[4];
    shs[gg][cl] = s; shq[gg][cl] = q2;
    __syncthreads();
    if (tid < 4) {
        float4 S = {0, 0, 0, 0}, Q = {0, 0, 0, 0};
        for (int g2 = 0; g2 < 64; g2++) {
            float4 a = shs[g2][tid], c = shq[g2][tid];
            S.x += a.x; S.y += a.y; S.z += a.z; S.w += a.w;
            Q.x += c.x; Q.y += c.y; Q.z += c.z; Q.w += c.w;
        }
        float4 gw4 = ((const float4*)gw)[qtr * 4 + tid];
        float4 gb4 = ((const float4*)gb)[qtr * 4 + tid];
        float4 sc, sf; float m, var;
        m = S.x / 1024.f; var = Q.x / 1024.f - m * m; sc.x = gw4.x * rsqrtf(var + 1e-5f); sf.x = gb4.x - m * sc.x;
        m = S.y / 1024.f; var = Q.y / 1024.f - m * m; sc.y = gw4.y * rsqrtf(var + 1e-5f); sf.y = gb4.y - m * sc.y;
        m = S.z / 1024.f; var = Q.z / 1024.f - m * m; sc.z = gw4.z * rsqrtf(var + 1e-5f); sf.z = gb4.z - m * sc.z;
        m = S.w / 1024.f; var = Q.w / 1024.f - m * m; sc.w = gw4.w * rsqrtf(var + 1e-5f); sf.w = gb4.w - m * sc.w;
        shsc[tid] = sc; shsf[tid] = sf;
    }
    __syncthreads();
    float4 sc = shsc[cl], sf = shsf[cl];
    float4 accp = {0, 0, 0, 0};
#pragma unroll 4
    for (int i = 0; i < 16; i++) {
        float4 a = ip[(gg * 16 + i) * 16 + c4];
        accp.x += fmaxf(a.x * sc.x + sf.x, 0.f);
        accp.y += fmaxf(a.y * sc.y + sf.y, 0.f);
        accp.z += fmaxf(a.z * sc.z + sf.z, 0.f);
        accp.w += fmaxf(a.w * sc.w + sf.w, 0.f);
    }
    __syncthreads();
    shs[gg][cl] = accp;
    __syncthreads();
    if (tid < 4) {
        float4 S = {0, 0, 0, 0};
        for (int g2 = 0; g2 < 64; g2++) {
            float4 a = shs[g2][cl == 0 ? tid : tid];
            a = shs[g2][tid];
            S.x += a.x; S.y += a.y; S.z += a.z; S.w += a.w;
        }
        int c0 = (qtr * 4 + tid) * 4;
        pool[b * CC + c0 + 0] = S.x / 1024.f;
        pool[b * CC + c0 + 1] = S.y / 1024.f;
        pool[b * CC + c0 + 2] = S.z / 1024.f;
        pool[b * CC + c0 + 3] = S.w / 1024.f;
    }
}

// ---------------- HMMA conv 4x4 stride2 pad1 (smem-staged A, h-phased) ------
template <int IH, int OH>
__global__ __launch_bounds__(128)
void conv4_mma(const __half* __restrict__ in, const __half* __restrict__ wpk,
               const float* __restrict__ bias, float* __restrict__ outF,
               __half* __restrict__ outH) {
    constexpr int IW = IH, OW = OH;
    constexpr int ROWS = (OH == 64) ? 6 : 10;
    extern __shared__ __half sA[];
    int q = blockIdx.x, b = blockIdx.y;
    int tid = threadIdx.x;
    int w = tid >> 5, lane = tid & 31;
    int gid = lane >> 2, tig = lane & 3;
    int oy, ox0, rbase;
    if (OH == 64) { oy = 2 * q + (w >> 1); ox0 = (w & 1) * 32; rbase = 4 * q - 1; }
    else          { oy = 4 * q + w;        ox0 = 0;            rbase = 8 * q - 1; }

    float acc[2][8][4];
#pragma unroll
    for (int mt = 0; mt < 2; mt++)
#pragma unroll
        for (int nt = 0; nt < 8; nt++)
#pragma unroll
            for (int j = 0; j < 4; j++) acc[mt][nt][j] = 0.f;

    const __half* inb = in + (size_t)b * IH * IW * 64;

#pragma unroll
    for (int h = 0; h < 2; h++) {
        if (h) __syncthreads();
        constexpr int NU2 = ROWS * IW * 8;
#pragma unroll 4
        for (int j = 0; j < NU2 / 128; j++) {
            int s = tid + 128 * j;
            int pxl = s >> 3, u2 = s & 7;
            int r = pxl / IW, x = pxl % IW;
            int iny = rbase + r;
            uint2 val = make_uint2(0u, 0u);
            if (iny >= 0 && iny < IH)
                val = *(const uint2*)(inb + ((size_t)iny * IW + x) * 64 + h * 32 + u2 * 4);
            *(uint2*)(&sA[pxl * 36 + u2 * 4]) = val;
        }
        __syncthreads();

#pragma unroll 2
        for (int tap = 0; tap < 16; tap++) {
            int dy = tap >> 2, dx = tap & 3;
            int rl = ((OH == 64) ? 2 * (w >> 1) : 2 * w) + dy;
            int xA[4]; bool ok[4];
#pragma unroll
            for (int u = 0; u < 4; u++) {
                int xi = (u >> 1) * 16 + (u & 1) * 8 + gid;
                int ix = 2 * (ox0 + xi) + dx - 1;
                xA[u] = ix;
                ok[u] = (ix >= 0) && (ix < IW);
            }
            uint32_t A[2][2][4];
#pragma unroll
            for (int kk = 0; kk < 2; kk++) {
                int ic = kk * 16 + 2 * tig;
                int a0 = (rl * IW + xA[0]) * 36 + ic;
                int a1 = (rl * IW + xA[1]) * 36 + ic;
                int a2 = (rl * IW + xA[2]) * 36 + ic;
                int a3 = (rl * IW + xA[3]) * 36 + ic;
                A[kk][0][0] = ok[0] ? *(const uint32_t*)(&sA[a0]) : 0u;
                A[kk][0][1] = ok[1] ? *(const uint32_t*)(&sA[a1]) : 0u;
                A[kk][0][2] = ok[0] ? *(const uint32_t*)(&sA[a0 + 8]) : 0u;
                A[kk][0][3] = ok[1] ? *(const uint32_t*)(&sA[a1 + 8]) : 0u;
                A[kk][1][0] = ok[2] ? *(const uint32_t*)(&sA[a2]) : 0u;
                A[kk][1][1] = ok[3] ? *(const uint32_t*)(&sA[a3]) : 0u;
                A[kk][1][2] = ok[2] ? *(const uint32_t*)(&sA[a2 + 8]) : 0u;
                A[kk][1][3] = ok[3] ? *(const uint32_t*)(&sA[a3 + 8]) : 0u;
            }
            const uint4* wp4 = (const uint4*)(wpk + (size_t)(tap * 2 + h) * 2048);
#pragma unroll
            for (int nt = 0; nt < 8; nt++) {
                uint4 wv = __ldg(wp4 + (nt * 8 + gid) * 4 + tig);
                mma_f16(acc[0][nt], A[0][0][0], A[0][0][1], A[0][0][2], A[0][0][3], wv.x, wv.y);
                mma_f16(acc[1][nt], A[0][1][0], A[0][1][1], A[0][1][2], A[0][1][3], wv.x, wv.y);
                mma_f16(acc[0][nt], A[1][0][0], A[1][0][1], A[1][0][2], A[1][0][3], wv.z, wv.w);
                mma_f16(acc[1][nt], A[1][1][0], A[1][1][1], A[1][1][2], A[1][1][3], wv.z, wv.w);
            }
        }
    }

#pragma unroll
    for (int mt = 0; mt < 2; mt++) {
#pragma unroll
        for (int rr = 0; rr < 2; rr++) {
            int x = ox0 + mt * 16 + gid + rr * 8;
            size_t base = ((size_t)(b * OH + oy) * OW + x) * 64;
#pragma unroll
            for (int nt = 0; nt < 8; nt++) {
                int oc = nt * 8 + 2 * tig;
                float2 v;
                v.x = acc[mt][nt][rr * 2 + 0] + __ldg(bias + oc);
                v.y = acc[mt][nt][rr * 2 + 1] + __ldg(bias + oc + 1);
                *(float2*)(outF + base + oc) = v;
                if (outH)
                    *(__half2*)(outH + base + oc) = __floats2half2_rn(v.x, v.y);
            }
        }
    }
}

// ---------------- conv1: 1->64, 3x3 VALID, fp32 NHWC out --------------------
__global__ __launch_bounds__(256)
void conv1_k(const float* __restrict__ x, const float* __restrict__ w,
             const float* __restrict__ bias, float* __restrict__ h1) {
    __shared__ float sIn[3 * 66];
    __shared__ float sW[576], sB[64];
    int slab = blockIdx.x, b = blockIdx.y;
    int row = slab >> 1, xbase = (slab & 1) * 64;
    int tid = threadIdx.x;
    for (int i = tid; i < 576; i += 256) sW[i] = w[i];
    if (tid < 64) sB[tid] = bias[tid];
    for (int i = tid; i < 198; i += 256) {
        int r = i / 66, c = i % 66;
        sIn[i] = x[((size_t)b * 130 + row + r) * 130 + xbase + c];
    }
    __syncthreads();
    int oc = tid & 63, pl = tid >> 6;
#pragma unroll 4
    for (int i = 0; i < 16; i++) {
        int lx = pl * 16 + i;
        float a = sB[oc];
#pragma unroll
        for (int ky = 0; ky < 3; ky++)
#pragma unroll
            for (int kx = 0; kx < 3; kx++)
                a = fmaf(sW[oc * 9 + ky * 3 + kx], sIn[ky * 66 + lx + kx], a);
        h1[((size_t)b * 16384 + row * 128 + xbase + lx) * 64 + oc] = a;
    }
}

// ---------------- GN + ReLU NHWC fp32 -> fp16 (downsampler, 2-pass) ---------
template <int NPX>
__global__ __launch_bounds__(256)
void gn_ds(const float* __restrict__ in, const float* __restrict__ gw,
           const float* __restrict__ gb, __half* __restrict__ out) {
    constexpr int PPG = NPX / 64;
    int b = blockIdx.x, qtr = blockIdx.y;
    int tid = threadIdx.x;
    int cl = tid & 3, c4 = qtr * 4 + cl, gg = tid >> 2;
    const float4* ip = (const float4*)in + (size_t)b * NPX * 16;
    float4 s = {0, 0, 0, 0}, q2 = {0, 0, 0, 0};
    for (int i = 0; i < PPG; i++) {
        int px = gg * PPG + i;
        float4 a = ip[(size_t)px * 16 + c4];
        s.x += a.x; s.y += a.y; s.z += a.z; s.w += a.w;
        q2.x += a.x * a.x; q2.y += a.y * a.y; q2.z += a.z * a.z; q2.w += a.w * a.w;
    }
    __shared__ float4 shs[64][4], shq[64][4];
    __shared__ float4 shsc[4], shsf[4];
    shs[gg][cl] = s; shq[gg][cl] = q2;
    __syncthreads();
    if (tid < 4) {
        float4 S = {0, 0, 0, 0}, Q = {0, 0, 0, 0};
        for (int g2 = 0; g2 < 64; g2++) {
            float4 a = shs[g2][tid], c = shq[g2][tid];
            S.x += a.x; S.y += a.y; S.z += a.z; S.w += a.w;
            Q.x += c.x; Q.y += c.y; Q.z += c.z; Q.w += c.w;
        }
        float4 gw4 = ((const float4*)gw)[qtr * 4 + tid];
        float4 gb4 = ((const float4*)gb)[qtr * 4 + tid];
        float4 sc, sf; float m, var; const float inv = 1.f / (float)NPX;
        m = S.x*inv; var = Q.x*inv - m*m; sc.x = gw4.x*rsqrtf(var+1e-5f); sf.x = gb4.x - m*sc.x;
        m = S.y*inv; var = Q.y*inv - m*m; sc.y = gw4.y*rsqrtf(var+1e-5f); sf.y = gb4.y - m*sc.y;
        m = S.z*inv; var = Q.z*inv - m*m; sc.z = gw4.z*rsqrtf(var+1e-5f); sf.z = gb4.z - m*sc.z;
        m = S.w*inv; var = Q.w*inv - m*m; sc.w = gw4.w*rsqrtf(var+1e-5f); sf.w = gb4.w - m*sc.w;
        shsc[tid] = sc; shsf[tid] = sf;
    }
    __syncthreads();
    float4 sc = shsc[cl], sf = shsf[cl];
    __half2* op = (__half2*)out + (size_t)b * NPX * 32;
    for (int i = 0; i < PPG; i++) {
        int px = gg * PPG + i;
        float4 a = ip[(size_t)px * 16 + c4];
        float rx = fmaxf(a.x * sc.x + sf.x, 0.f);
        float ry = fmaxf(a.y * sc.y + sf.y, 0.f);
        float rz = fmaxf(a.z * sc.z + sf.z, 0.f);
        float rw = fmaxf(a.w * sc.w + sf.w, 0.f);
        op[(size_t)px * 32 + c4 * 2 + 0] = __floats2half2_rn(rx, ry);
        op[(size_t)px * 32 + c4 * 2 + 1] = __floats2half2_rn(rz, rw);
    }
}

// ---------------- head linear ------------------------------------------------
__global__ __launch_bounds__(256)
void linear_k(const float* __restrict__ pool, const float* __restrict__ W,
              const float* __restrict__ bias, float* __restrict__ out) {
    int idx = blockIdx.x * 256 + threadIdx.x;
    if (idx >= BB * 10) return;
    int b = idx / 10, n = idx % 10;
    float acc = bias[n];
#pragma unroll 8
    for (int c = 0; c < CC; c++) acc += pool[b * CC + c] * W[n * CC + c];
    out[idx] = acc;
}

// ---------------- launch -----------------------------------------------------
extern "C" void kernel_launch(void* const* d_in, const int* in_sizes, int n_in,
                              void* d_out, int out_size) {
    const float* x      = (const float*)d_in[0];
    const float* ds_w1  = (const float*)d_in[1];
    const float* ds_b1  = (const float*)d_in[2];
    const float* ds_n1w = (const float*)d_in[3];
    const float* ds_n1b = (const float*)d_in[4];
    const float* ds_w2  = (const float*)d_in[5];
    const float* ds_b2  = (const float*)d_in[6];
    const float* ds_n2w = (const float*)d_in[7];
    const float* ds_n2b = (const float*)d_in[8];
    const float* ds_w3  = (const float*)d_in[9];
    const float* ds_b3  = (const float*)d_in[10];
    const float* ode_w1 = (const float*)d_in[11];
    const float* ode_b1 = (const float*)d_in[12];
    const float* ode_n1w= (const float*)d_in[13];
    const float* ode_n1b= (const float*)d_in[14];
    const float* ode_w2 = (const float*)d_in[15];
    const float* ode_b2 = (const float*)d_in[16];
    const float* ode_n2w= (const float*)d_in[17];
    const float* ode_n2b= (const float*)d_in[18];
    const float* head_nw= (const float*)d_in[19];
    const float* head_nb= (const float*)d_in[20];
    const float* head_W = (const float*)d_in[21];
    const float* head_b = (const float*)d_in[22];
    float* out = (float*)d_out;

    float *h1, *h2, *z, *ka, *pool, *wcls;
    __half *h1h, *h2h, *zh, *u, *ga, *bpk, *b4;
    float2 *scb;
    cudaGetSymbolAddress((void**)&h1,  g_h1);
    cudaGetSymbolAddress((void**)&h1h, g_h1h);
    cudaGetSymbolAddress((void**)&h2,  g_h2);
    cudaGetSymbolAddress((void**)&h2h, g_h2h);
    cudaGetSymbolAddress((void**)&z,   g_z);
    cudaGetSymbolAddress((void**)&zh,  g_zh);
    cudaGetSymbolAddress((void**)&u,   g_u);
    cudaGetSymbolAddress((void**)&ga,  g_ga);
    cudaGetSymbolAddress((void**)&ka,  g_ka);
    cudaGetSymbolAddress((void**)&scb, g_scb);
    cudaGetSymbolAddress((void**)&pool,g_pool);
    cudaGetSymbolAddress((void**)&bpk, g_BpackH);
    cudaGetSymbolAddress((void**)&b4,  g_B4);
    cudaGetSymbolAddress((void**)&wcls,g_Wcls);

    static int smem_set = 0;
    if (!smem_set) {
        cudaFuncSetAttribute(conv4_mma<128, 64>,
                             cudaFuncAttributeMaxDynamicSharedMemorySize, 6 * 128 * 36 * 2);
        cudaFuncSetAttribute(conv4_mma<64, 32>,
                             cudaFuncAttributeMaxDynamicSharedMemorySize, 10 * 64 * 36 * 2);
        smem_set = 1;
    }

    prep_w<<<512, 256>>>(ode_w1, ode_w2, ds_w2, ds_w3);

    // ---- downsampler ----
    conv1_k<<<dim3(256, 64), 256>>>(x, ds_w1, ds_b1, h1);
    gn_ds<16384><<<dim3(64, 4), 256>>>(h1, ds_n1w, ds_n1b, h1h);
    conv4_mma<128, 64><<<dim3(32, 64), 128, 6 * 128 * 36 * 2>>>(h1h, b4, ds_b2, h2, nullptr);
    gn_ds<4096><<<dim3(64, 4), 256>>>(h2, ds_n2w, ds_n2b, h2h);
    conv4_mma<64, 32><<<dim3(8, 64), 128, 10 * 64 * 36 * 2>>>(h2h, b4 + 32 * 2048, ds_b3, z, zh);

    // ---- ODE: 10 RK4 steps (stats kernel + normalize-in-conv) ----
    dim3 cg(8, 64);
    const __half* w1p = bpk;
    const __half* w2p = bpk + 18 * 2048;
    const float* wc1 = wcls;
    const float* wc2 = wcls + 9 * 64;
    for (int i = 0; i < 10; i++) {
        float t = (float)i * 0.1f;
        // k1
        gn_stath<<<64, 256>>>(zh, ode_n1w, ode_n1b, scb);
        ode_conv_mma<0><<<cg, 128>>>(zh, scb, w1p, t,        ode_b1, wc1, u,  ka, z, zh);
        gn_stath<<<64, 256>>>(u,  ode_n2w, ode_n2b, scb);
        ode_conv_mma<1><<<cg, 128>>>(u,  scb, w2p, t,        ode_b2, wc2, ga, ka, z, zh);
        // k2
        gn_stath<<<64, 256>>>(ga, ode_n1w, ode_n1b, scb);
        ode_conv_mma<0><<<cg, 128>>>(ga, scb, w1p, t + .05f, ode_b1, wc1, u,  ka, z, zh);
        gn_stath<<<64, 256>>>(u,  ode_n2w, ode_n2b, scb);
        ode_conv_mma<2><<<cg, 128>>>(u,  scb, w2p, t + .05f, ode_b2, wc2, ga, ka, z, zh);
        // k3
        gn_stath<<<64, 256>>>(ga, ode_n1w, ode_n1b, scb);
        ode_conv_mma<0><<<cg, 128>>>(ga, scb, w1p, t + .05f, ode_b1, wc1, u,  ka, z, zh);
        gn_stath<<<64, 256>>>(u,  ode_n2w, ode_n2b, scb);
        ode_conv_mma<3><<<cg, 128>>>(u,  scb, w2p, t + .05f, ode_b2, wc2, ga, ka, z, zh);
        // k4
        gn_stath<<<64, 256>>>(ga, ode_n1w, ode_n1b, scb);
        ode_conv_mma<0><<<cg, 128>>>(ga, scb, w1p, t + .1f,  ode_b1, wc1, u,  ka, z, zh);
        gn_stath<<<64, 256>>>(u,  ode_n2w, ode_n2b, scb);
        ode_conv_mma<4><<<cg, 128>>>(u,  scb, w2p, t + .1f,  ode_b2, wc2, ga, ka, z, zh);
    }

    // ---- head ----
    gn_pool<<<dim3(64, 4), 256>>>(z, head_nw, head_nb, pool);
    linear_k<<<(BB * 10 + 255) / 256, 256>>>(pool, head_W, head_b, out);
}

// round 16
// speedup vs baseline: 1.1608x; 1.1608x over previous
#include <cuda_runtime.h>
#include <cuda_fp16.h>
#include <cstdint>

#define BB 64
#define CC 64
#define DT6 (0.1f/6.0f)

// ---------------- scratch (device globals) ---------------------------------
static __device__ float  g_h1 [BB*128*128*64];   // fp32 NHWC
static __device__ __half g_h1h[BB*128*128*64];   // fp16 NHWC
static __device__ float  g_h2 [BB*64*64*64];     // fp32 NHWC
static __device__ __half g_h2h[BB*64*64*64];     // fp16 NHWC
static __device__ float  g_z  [BB*1024*64];      // fp32 NHWC (ODE state)
static __device__ __half g_zh [BB*1024*64];      // fp16 shadow of z
static __device__ __half g_u  [BB*1024*64];      // fp16: convA output (GN2 in)
static __device__ __half g_ga [BB*1024*64];      // fp16: z+alpha*k (GN1 in)
static __device__ float  g_ka [BB*1024*64];      // fp32 RK4 accumulator
static __device__ __half g_g  [BB*1024*64];      // fp16 NHWC conv input
static __device__ float  g_pool[BB*CC];
// packed B: [chunk][nt][gid][tig][4 b32]
static __device__ __half g_BpackH[36*2048];      // ODE weights
static __device__ __half g_B4[2*32*2048];        // conv4 weights
static __device__ float  g_Wcls[2*3*3*64];       // time-channel border sums

// ---------------- fp16 MMA -------------------------------------------------
__device__ __forceinline__ void mma_f16(float* c, uint32_t a0, uint32_t a1,
                                        uint32_t a2, uint32_t a3,
                                        uint32_t b0, uint32_t b1) {
    asm volatile(
        "mma.sync.aligned.m16n8k16.row.col.f32.f16.f16.f32 "
        "{%0,%1,%2,%3},{%4,%5,%6,%7},{%8,%9},{%0,%1,%2,%3};"
        : "+f"(c[0]), "+f"(c[1]), "+f"(c[2]), "+f"(c[3])
        : "r"(a0), "r"(a1), "r"(a2), "r"(a3), "r"(b0), "r"(b1));
}

// ---------------- weight prepack -------------------------------------------
__global__ __launch_bounds__(256)
void prep_w(const float* __restrict__ w1, const float* __restrict__ w2,
            const float* __restrict__ w4a, const float* __restrict__ w4b) {
    int i = blockIdx.x * 256 + threadIdx.x;
    if (i < 36 * 2048) {                    // ODE conv weights
        int e = i & 1, w4 = (i >> 1) & 3, tig = (i >> 3) & 3;
        int gid = (i >> 5) & 7, nt = (i >> 8) & 7;
        int c = i >> 11;                    // cv*18 + s9*2 + h
        int h = c & 1, s9 = (c >> 1) % 9, cv = c / 18;
        int dy = s9 / 3, dx = s9 % 3;
        int kk = w4 >> 1, bsel = w4 & 1;
        int k = kk * 16 + 2 * tig + bsel * 8 + e;
        int oc = nt * 8 + gid;
        const float* w = cv ? w2 : w1;
        int icg = h * 32 + k;
        g_BpackH[i] = __float2half(w[((oc * 65 + icg + 1) * 3 + dy) * 3 + dx]);
    }
    if (i < 2 * 32 * 2048) {                // conv4 weights
        int e = i & 1, w4 = (i >> 1) & 3, tig = (i >> 3) & 3;
        int gid = (i >> 5) & 7, nt = (i >> 8) & 7;
        int tix = (i >> 11) & 31;           // tap*2 + h
        int cv = i >> 16;
        int h = tix & 1, tap = tix >> 1;
        int ky = tap >> 2, kx = tap & 3;
        int kk = w4 >> 1, bsel = w4 & 1;
        int k = kk * 16 + 2 * tig + bsel * 8 + e;
        int oc = nt * 8 + gid;
        const float* w = cv ? w4b : w4a;
        int ic = h * 32 + k;
        g_B4[i] = __float2half(w[((oc * 64 + ic) * 4 + ky) * 4 + kx]);
    }
    if (i < 2 * 3 * 3 * 64) {               // time-channel border-class sums
        int oc = i & 63;
        int t2 = i >> 6;
        int xs = t2 % 3, ys = (t2 / 3) % 3, cv = t2 / 9;
        const float* w = cv ? w2 : w1;
        float s = 0.f;
        for (int dy = 0; dy < 3; dy++)
            for (int dx = 0; dx < 3; dx++) {
                bool okY = !((ys == 0 && dy == 0) || (ys == 2 && dy == 2));
                bool okX = !((xs == 0 && dx == 0) || (xs == 2 && dx == 2));
                if (okY && okX) s += w[(oc * 65 * 3 + dy) * 3 + dx];
            }
        g_Wcls[((cv * 3 + ys) * 3 + xs) * 64 + oc] = s;
    }
}

// ---------------- HMMA ODE conv 3x3 pad1 (smem A, fp16 outb) ----------------
// MODE 0 (convA): outb = fp16(v)
// MODE 1 (k1):    ka = v;   outb = fp16(z + 0.05v)
// MODE 2 (k2):    ka += 2v; outb = fp16(z + 0.05v)
// MODE 3 (k3):    ka += 2v; outb = fp16(z + 0.10v)
// MODE 4 (k4):    z += DT6*(ka+v); zh = fp16(z')
template <int MODE>
__global__ __launch_bounds__(128)
void ode_conv_mma(const __half* __restrict__ g, const __half* __restrict__ wpk,
                  float t, const float* __restrict__ bias,
                  const float* __restrict__ wcls,
                  __half* __restrict__ outb, float* __restrict__ ka,
                  float* __restrict__ z, __half* __restrict__ zh) {
    __shared__ __half sA[192 * 72];          // 6 rows x 32 x, stride 72 halves
    int q = blockIdx.x, b = blockIdx.y;
    int tid = threadIdx.x;
    int w = tid >> 5, lane = tid & 31;
    int gid = lane >> 2, tig = lane & 3;
    int y = 4 * q + w;

    const __half* gb = g + (size_t)b * 65536;
#pragma unroll
    for (int j = 0; j < 12; j++) {
        int s = tid + 128 * j;
        int px = s >> 3, c8 = s & 7;
        int x = px & 31, yy = px >> 5;
        int yg = 4 * q - 1 + yy;
        uint4 v = make_uint4(0u, 0u, 0u, 0u);
        if (yg >= 0 && yg < 32)
            v = *(const uint4*)(gb + ((size_t)yg * 32 + x) * 64 + c8 * 8);
        *(uint4*)(&sA[px * 72 + c8 * 8]) = v;
    }
    __syncthreads();

    float acc[2][8][4];
#pragma unroll
    for (int mt = 0; mt < 2; mt++)
#pragma unroll
        for (int nt = 0; nt < 8; nt++)
#pragma unroll
            for (int j = 0; j < 4; j++) acc[mt][nt][j] = 0.f;

#pragma unroll
    for (int c = 0; c < 18; c++) {
        int s9 = c >> 1, h = c & 1;
        int dy = s9 / 3, dx = s9 % 3;
        int yyl = w + dy;

        int xA0 = gid + dx - 1;
        int xA1 = xA0 + 8, xA2 = xA0 + 16, xA3 = xA0 + 24;
        bool ok0 = (xA0 >= 0) && (xA0 < 32);
        bool ok1 = (xA1 >= 0) && (xA1 < 32);
        bool ok2 = (xA2 >= 0) && (xA2 < 32);
        bool ok3 = (xA3 >= 0) && (xA3 < 32);
        int r0 = (yyl * 32 + xA0) * 72 + h * 32;
        int r1 = (yyl * 32 + xA1) * 72 + h * 32;
        int r2 = (yyl * 32 + xA2) * 72 + h * 32;
        int r3 = (yyl * 32 + xA3) * 72 + h * 32;

        uint32_t A[2][2][4];
#pragma unroll
        for (int kk = 0; kk < 2; kk++) {
            int ic = kk * 16 + 2 * tig;
            A[kk][0][0] = ok0 ? *(const uint32_t*)(&sA[r0 + ic]) : 0u;
            A[kk][0][1] = ok1 ? *(const uint32_t*)(&sA[r1 + ic]) : 0u;
            A[kk][0][2] = ok0 ? *(const uint32_t*)(&sA[r0 + ic + 8]) : 0u;
            A[kk][0][3] = ok1 ? *(const uint32_t*)(&sA[r1 + ic + 8]) : 0u;
            A[kk][1][0] = ok2 ? *(const uint32_t*)(&sA[r2 + ic]) : 0u;
            A[kk][1][1] = ok3 ? *(const uint32_t*)(&sA[r3 + ic]) : 0u;
            A[kk][1][2] = ok2 ? *(const uint32_t*)(&sA[r2 + ic + 8]) : 0u;
            A[kk][1][3] = ok3 ? *(const uint32_t*)(&sA[r3 + ic + 8]) : 0u;
        }

        const uint4* wp4 = (const uint4*)(wpk + (size_t)c * 2048);
#pragma unroll
        for (int nt = 0; nt < 8; nt++) {
            uint4 wv = __ldg(wp4 + (nt * 8 + gid) * 4 + tig);
            mma_f16(acc[0][nt], A[0][0][0], A[0][0][1], A[0][0][2], A[0][0][3], wv.x, wv.y);
            mma_f16(acc[1][nt], A[0][1][0], A[0][1][1], A[0][1][2], A[0][1][3], wv.x, wv.y);
            mma_f16(acc[0][nt], A[1][0][0], A[1][0][1], A[1][0][2], A[1][0][3], wv.z, wv.w);
            mma_f16(acc[1][nt], A[1][1][0], A[1][1][1], A[1][1][2], A[1][1][3], wv.z, wv.w);
        }
    }

    int ys = (y == 0) ? 0 : ((y == 31) ? 2 : 1);
    const float* wcy = wcls + ys * 3 * 64;
#pragma unroll
    for (int mt = 0; mt < 2; mt++) {
#pragma unroll
        for (int rr = 0; rr < 2; rr++) {
            int x = mt * 16 + gid + rr * 8;
            int xs = (x == 0) ? 0 : ((x == 31) ? 2 : 1);
            const float* wcx = wcy + xs * 64;
            size_t base = ((size_t)b * 1024 + y * 32 + x) * 64;
#pragma unroll
            for (int nt = 0; nt < 8; nt++) {
                int oc = nt * 8 + 2 * tig;
                float2 v;
                v.x = acc[mt][nt][rr * 2 + 0] + __ldg(bias + oc) + t * __ldg(wcx + oc);
                v.y = acc[mt][nt][rr * 2 + 1] + __ldg(bias + oc + 1) + t * __ldg(wcx + oc + 1);
                if (MODE == 0) {
                    *(__half2*)(outb + base + oc) = __floats2half2_rn(v.x, v.y);
                } else if (MODE == 1) {
                    *(float2*)(ka + base + oc) = v;
                    float2 zz = *(const float2*)(z + base + oc);
                    *(__half2*)(outb + base + oc) =
                        __floats2half2_rn(zz.x + 0.05f * v.x, zz.y + 0.05f * v.y);
                } else if (MODE == 2 || MODE == 3) {
                    float2 a = *(const float2*)(ka + base + oc);
                    a.x += 2.f * v.x; a.y += 2.f * v.y;
                    *(float2*)(ka + base + oc) = a;
                    const float alpha = (MODE == 2) ? 0.05f : 0.1f;
                    float2 zz = *(const float2*)(z + base + oc);
                    *(__half2*)(outb + base + oc) =
                        __floats2half2_rn(zz.x + alpha * v.x, zz.y + alpha * v.y);
                } else {
                    float2 a = *(const float2*)(ka + base + oc);
                    float2 zz = *(const float2*)(z + base + oc);
                    zz.x += DT6 * (a.x + v.x);
                    zz.y += DT6 * (a.y + v.y);
                    *(float2*)(z + base + oc) = zz;
                    *(__half2*)(zh + base + oc) = __floats2half2_rn(zz.x, zz.y);
                }
            }
        }
    }
}

// ---------------- single-pass GN + ReLU, fp16 in -> fp16 --------------------
__global__ __launch_bounds__(256)
void gn_sph(const __half* __restrict__ in, const float* __restrict__ gw,
            const float* __restrict__ gb, __half* __restrict__ out) {
    int b = blockIdx.x, qtr = blockIdx.y;
    int tid = threadIdx.x;
    int cl = tid & 3, c4 = qtr * 4 + cl, gg = tid >> 2;
    const uint2* ip = (const uint2*)in + (size_t)b * 16384;

    uint2 raw[16];
    float4 s = {0, 0, 0, 0}, q2 = {0, 0, 0, 0};
#pragma unroll
    for (int i = 0; i < 16; i++) {
        raw[i] = ip[(gg * 16 + i) * 16 + c4];
        float2 fa = __half22float2(*(__half2*)&raw[i].x);
        float2 fb = __half22float2(*(__half2*)&raw[i].y);
        s.x += fa.x; s.y += fa.y; s.z += fb.x; s.w += fb.y;
        q2.x += fa.x * fa.x; q2.y += fa.y * fa.y;
        q2.z += fb.x * fb.x; q2.w += fb.y * fb.y;
    }
    __shared__ float4 shs[64][4], shq[64][4];
    __shared__ float4 shsc[4], shsf[4];
    shs[gg][cl] = s; shq[gg][cl] = q2;
    __syncthreads();
    if (tid < 4) {
        float4 S = {0, 0, 0, 0}, Q = {0, 0, 0, 0};
        for (int g2 = 0; g2 < 64; g2++) {
            float4 a = shs[g2][tid], c = shq[g2][tid];
            S.x += a.x; S.y += a.y; S.z += a.z; S.w += a.w;
            Q.x += c.x; Q.y += c.y; Q.z += c.z; Q.w += c.w;
        }
        float4 gw4 = ((const float4*)gw)[qtr * 4 + tid];
        float4 gb4 = ((const float4*)gb)[qtr * 4 + tid];
        float4 sc, sf;
        float m, var;
        m = S.x / 1024.f; var = Q.x / 1024.f - m * m; sc.x = gw4.x * rsqrtf(var + 1e-5f); sf.x = gb4.x - m * sc.x;
        m = S.y / 1024.f; var = Q.y / 1024.f - m * m; sc.y = gw4.y * rsqrtf(var + 1e-5f); sf.y = gb4.y - m * sc.y;
        m = S.z / 1024.f; var = Q.z / 1024.f - m * m; sc.z = gw4.z * rsqrtf(var + 1e-5f); sf.z = gb4.z - m * sc.z;
        m = S.w / 1024.f; var = Q.w / 1024.f - m * m; sc.w = gw4.w * rsqrtf(var + 1e-5f); sf.w = gb4.w - m * sc.w;
        shsc[tid] = sc; shsf[tid] = sf;
    }
    __syncthreads();
    float4 sc = shsc[cl], sf = shsf[cl];
    __half2* op = (__half2*)out + (size_t)b * 32768;
#pragma unroll
    for (int i = 0; i < 16; i++) {
        int px = gg * 16 + i;
        float2 fa = __half22float2(*(__half2*)&raw[i].x);
        float2 fb = __half22float2(*(__half2*)&raw[i].y);
        float rx = fmaxf(fmaf(fa.x, sc.x, sf.x), 0.f);
        float ry = fmaxf(fmaf(fa.y, sc.y, sf.y), 0.f);
        float rz = fmaxf(fmaf(fb.x, sc.z, sf.z), 0.f);
        float rw = fmaxf(fmaf(fb.y, sc.w, sf.w), 0.f);
        op[px * 32 + c4 * 2 + 0] = __floats2half2_rn(rx, ry);
        op[px * 32 + c4 * 2 + 1] = __floats2half2_rn(rz, rw);
    }
}

// ---------------- GN + ReLU + pool (head only, fp32 z) ----------------------
__global__ __launch_bounds__(256)
void gn_pool(const float* __restrict__ in, const float* __restrict__ gw,
             const float* __restrict__ gb, float* __restrict__ pool) {
    int b = blockIdx.x, qtr = blockIdx.y;
    int tid = threadIdx.x;
    int cl = tid & 3, c4 = qtr * 4 + cl, gg = tid >> 2;
    const float4* ip = (const float4*)in + (size_t)b * 16384;
    float4 s = {0, 0, 0, 0}, q2 = {0, 0, 0, 0};
#pragma unroll 4
    for (int i = 0; i < 16; i++) {
        float4 a = ip[(gg * 16 + i) * 16 + c4];
        s.x += a.x; s.y += a.y; s.z += a.z; s.w += a.w;
        q2.x += a.x * a.x; q2.y += a.y * a.y; q2.z += a.z * a.z; q2.w += a.w * a.w;
    }
    __shared__ float4 shs[64][4], shq[64][4];
    __shared__ float4 shsc[4], shsf[4];
    shs[gg][cl] = s; shq[gg][cl] = q2;
    __syncthreads();
    if (tid < 4) {
        float4 S = {0, 0, 0, 0}, Q = {0, 0, 0, 0};
        for (int g2 = 0; g2 < 64; g2++) {
            float4 a = shs[g2][tid], c = shq[g2][tid];
            S.x += a.x; S.y += a.y; S.z += a.z; S.w += a.w;
            Q.x += c.x; Q.y += c.y; Q.z += c.z; Q.w += c.w;
        }
        float4 gw4 = ((const float4*)gw)[qtr * 4 + tid];
        float4 gb4 = ((const float4*)gb)[qtr * 4 + tid];
        float4 sc, sf; float m, var;
        m = S.x / 1024.f; var = Q.x / 1024.f - m * m; sc.x = gw4.x * rsqrtf(var + 1e-5f); sf.x = gb4.x - m * sc.x;
        m = S.y / 1024.f; var = Q.y / 1024.f - m * m; sc.y = gw4.y * rsqrtf(var + 1e-5f); sf.y = gb4.y - m * sc.y;
        m = S.z / 1024.f; var = Q.z / 1024.f - m * m; sc.z = gw4.z * rsqrtf(var + 1e-5f); sf.z = gb4.z - m * sc.z;
        m = S.w / 1024.f; var = Q.w / 1024.f - m * m; sc.w = gw4.w * rsqrtf(var + 1e-5f); sf.w = gb4.w - m * sc.w;
        shsc[tid] = sc; shsf[tid] = sf;
    }
    __syncthreads();
    float4 sc = shsc[cl], sf = shsf[cl];
    float4 accp = {0, 0, 0, 0};
#pragma unroll 4
    for (int i = 0; i < 16; i++) {
        float4 a = ip[(gg * 16 + i) * 16 + c4];
        accp.x += fmaxf(a.x * sc.x + sf.x, 0.f);
        accp.y += fmaxf(a.y * sc.y + sf.y, 0.f);
        accp.z += fmaxf(a.z * sc.z + sf.z, 0.f);
        accp.w += fmaxf(a.w * sc.w + sf.w, 0.f);
    }
    __syncthreads();
    shs[gg][cl] = accp;
    __syncthreads();
    if (tid < 4) {
        float4 S = {0, 0, 0, 0};
        for (int g2 = 0; g2 < 64; g2++) {
            float4 a = shs[g2][tid];
            S.x += a.x; S.y += a.y; S.z += a.z; S.w += a.w;
        }
        int c0 = (qtr * 4 + tid) * 4;
        pool[b * CC + c0 + 0] = S.x / 1024.f;
        pool[b * CC + c0 + 1] = S.y / 1024.f;
        pool[b * CC + c0 + 2] = S.z / 1024.f;
        pool[b * CC + c0 + 3] = S.w / 1024.f;
    }
}

// ---------------- HMMA conv 4x4 stride2 pad1 (smem-staged A, h-phased) ------
template <int IH, int OH>
__global__ __launch_bounds__(128)
void conv4_mma(const __half* __restrict__ in, const __half* __restrict__ wpk,
               const float* __restrict__ bias, float* __restrict__ outF,
               __half* __restrict__ outH) {
    constexpr int IW = IH, OW = OH;
    constexpr int ROWS = (OH == 64) ? 6 : 10;
    extern __shared__ __half sA[];
    int q = blockIdx.x, b = blockIdx.y;
    int tid = threadIdx.x;
    int w = tid >> 5, lane = tid & 31;
    int gid = lane >> 2, tig = lane & 3;
    int oy, ox0, rbase;
    if (OH == 64) { oy = 2 * q + (w >> 1); ox0 = (w & 1) * 32; rbase = 4 * q - 1; }
    else          { oy = 4 * q + w;        ox0 = 0;            rbase = 8 * q - 1; }

    float acc[2][8][4];
#pragma unroll
    for (int mt = 0; mt < 2; mt++)
#pragma unroll
        for (int nt = 0; nt < 8; nt++)
#pragma unroll
            for (int j = 0; j < 4; j++) acc[mt][nt][j] = 0.f;

    const __half* inb = in + (size_t)b * IH * IW * 64;

#pragma unroll
    for (int h = 0; h < 2; h++) {
        if (h) __syncthreads();
        constexpr int NU2 = ROWS * IW * 8;
#pragma unroll 4
        for (int j = 0; j < NU2 / 128; j++) {
            int s = tid + 128 * j;
            int pxl = s >> 3, u2 = s & 7;
            int r = pxl / IW, x = pxl % IW;
            int iny = rbase + r;
            uint2 val = make_uint2(0u, 0u);
            if (iny >= 0 && iny < IH)
                val = *(const uint2*)(inb + ((size_t)iny * IW + x) * 64 + h * 32 + u2 * 4);
            *(uint2*)(&sA[pxl * 36 + u2 * 4]) = val;
        }
        __syncthreads();

#pragma unroll 2
        for (int tap = 0; tap < 16; tap++) {
            int dy = tap >> 2, dx = tap & 3;
            int rl = ((OH == 64) ? 2 * (w >> 1) : 2 * w) + dy;
            int xA[4]; bool ok[4];
#pragma unroll
            for (int u = 0; u < 4; u++) {
                int xi = (u >> 1) * 16 + (u & 1) * 8 + gid;
                int ix = 2 * (ox0 + xi) + dx - 1;
                xA[u] = ix;
                ok[u] = (ix >= 0) && (ix < IW);
            }
            uint32_t A[2][2][4];
#pragma unroll
            for (int kk = 0; kk < 2; kk++) {
                int ic = kk * 16 + 2 * tig;
                int a0 = (rl * IW + xA[0]) * 36 + ic;
                int a1 = (rl * IW + xA[1]) * 36 + ic;
                int a2 = (rl * IW + xA[2]) * 36 + ic;
                int a3 = (rl * IW + xA[3]) * 36 + ic;
                A[kk][0][0] = ok[0] ? *(const uint32_t*)(&sA[a0]) : 0u;
                A[kk][0][1] = ok[1] ? *(const uint32_t*)(&sA[a1]) : 0u;
                A[kk][0][2] = ok[0] ? *(const uint32_t*)(&sA[a0 + 8]) : 0u;
                A[kk][0][3] = ok[1] ? *(const uint32_t*)(&sA[a1 + 8]) : 0u;
                A[kk][1][0] = ok[2] ? *(const uint32_t*)(&sA[a2]) : 0u;
                A[kk][1][1] = ok[3] ? *(const uint32_t*)(&sA[a3]) : 0u;
                A[kk][1][2] = ok[2] ? *(const uint32_t*)(&sA[a2 + 8]) : 0u;
                A[kk][1][3] = ok[3] ? *(const uint32_t*)(&sA[a3 + 8]) : 0u;
            }
            const uint4* wp4 = (const uint4*)(wpk + (size_t)(tap * 2 + h) * 2048);
#pragma unroll
            for (int nt = 0; nt < 8; nt++) {
                uint4 wv = __ldg(wp4 + (nt * 8 + gid) * 4 + tig);
                mma_f16(acc[0][nt], A[0][0][0], A[0][0][1], A[0][0][2], A[0][0][3], wv.x, wv.y);
                mma_f16(acc[1][nt], A[0][1][0], A[0][1][1], A[0][1][2], A[0][1][3], wv.x, wv.y);
                mma_f16(acc[0][nt], A[1][0][0], A[1][0][1], A[1][0][2], A[1][0][3], wv.z, wv.w);
                mma_f16(acc[1][nt], A[1][1][0], A[1][1][1], A[1][1][2], A[1][1][3], wv.z, wv.w);
            }
        }
    }

#pragma unroll
    for (int mt = 0; mt < 2; mt++) {
#pragma unroll
        for (int rr = 0; rr < 2; rr++) {
            int x = ox0 + mt * 16 + gid + rr * 8;
            size_t base = ((size_t)(b * OH + oy) * OW + x) * 64;
#pragma unroll
            for (int nt = 0; nt < 8; nt++) {
                int oc = nt * 8 + 2 * tig;
                float2 v;
                v.x = acc[mt][nt][rr * 2 + 0] + __ldg(bias + oc);
                v.y = acc[mt][nt][rr * 2 + 1] + __ldg(bias + oc + 1);
                *(float2*)(outF + base + oc) = v;
                if (outH)
                    *(__half2*)(outH + base + oc) = __floats2half2_rn(v.x, v.y);
            }
        }
    }
}

// ---------------- conv1: 1->64, 3x3 VALID, fp32 NHWC out --------------------
__global__ __launch_bounds__(256)
void conv1_k(const float* __restrict__ x, const float* __restrict__ w,
             const float* __restrict__ bias, float* __restrict__ h1) {
    __shared__ float sIn[3 * 66];
    __shared__ float sW[576], sB[64];
    int slab = blockIdx.x, b = blockIdx.y;
    int row = slab >> 1, xbase = (slab & 1) * 64;
    int tid = threadIdx.x;
    for (int i = tid; i < 576; i += 256) sW[i] = w[i];
    if (tid < 64) sB[tid] = bias[tid];
    for (int i = tid; i < 198; i += 256) {
        int r = i / 66, c = i % 66;
        sIn[i] = x[((size_t)b * 130 + row + r) * 130 + xbase + c];
    }
    __syncthreads();
    int oc = tid & 63, pl = tid >> 6;
#pragma unroll 4
    for (int i = 0; i < 16; i++) {
        int lx = pl * 16 + i;
        float a = sB[oc];
#pragma unroll
        for (int ky = 0; ky < 3; ky++)
#pragma unroll
            for (int kx = 0; kx < 3; kx++)
                a = fmaf(sW[oc * 9 + ky * 3 + kx], sIn[ky * 66 + lx + kx], a);
        h1[((size_t)b * 16384 + row * 128 + xbase + lx) * 64 + oc] = a;
    }
}

// ---------------- GN + ReLU NHWC fp32 -> fp16 (downsampler, 2-pass) ---------
template <int NPX>
__global__ __launch_bounds__(256)
void gn_ds(const float* __restrict__ in, const float* __restrict__ gw,
           const float* __restrict__ gb, __half* __restrict__ out) {
    constexpr int PPG = NPX / 64;
    int b = blockIdx.x, qtr = blockIdx.y;
    int tid = threadIdx.x;
    int cl = tid & 3, c4 = qtr * 4 + cl, gg = tid >> 2;
    const float4* ip = (const float4*)in + (size_t)b * NPX * 16;
    float4 s = {0, 0, 0, 0}, q2 = {0, 0, 0, 0};
    for (int i = 0; i < PPG; i++) {
        int px = gg * PPG + i;
        float4 a = ip[(size_t)px * 16 + c4];
        s.x += a.x; s.y += a.y; s.z += a.z; s.w += a.w;
        q2.x += a.x * a.x; q2.y += a.y * a.y; q2.z += a.z * a.z; q2.w += a.w * a.w;
    }
    __shared__ float4 shs[64][4], shq[64][4];
    __shared__ float4 shsc[4], shsf[4];
    shs[gg][cl] = s; shq[gg][cl] = q2;
    __syncthreads();
    if (tid < 4) {
        float4 S = {0, 0, 0, 0}, Q = {0, 0, 0, 0};
        for (int g2 = 0; g2 < 64; g2++) {
            float4 a = shs[g2][tid], c = shq[g2][tid];
            S.x += a.x; S.y += a.y; S.z += a.z; S.w += a.w;
            Q.x += c.x; Q.y += c.y; Q.z += c.z; Q.w += c.w;
        }
        float4 gw4 = ((const float4*)gw)[qtr * 4 + tid];
        float4 gb4 = ((const float4*)gb)[qtr * 4 + tid];
        float4 sc, sf; float m, var; const float inv = 1.f / (float)NPX;
        m = S.x*inv; var = Q.x*inv - m*m; sc.x = gw4.x*rsqrtf(var+1e-5f); sf.x = gb4.x - m*sc.x;
        m = S.y*inv; var = Q.y*inv - m*m; sc.y = gw4.y*rsqrtf(var+1e-5f); sf.y = gb4.y - m*sc.y;
        m = S.z*inv; var = Q.z*inv - m*m; sc.z = gw4.z*rsqrtf(var+1e-5f); sf.z = gb4.z - m*sc.z;
        m = S.w*inv; var = Q.w*inv - m*m; sc.w = gw4.w*rsqrtf(var+1e-5f); sf.w = gb4.w - m*sc.w;
        shsc[tid] = sc; shsf[tid] = sf;
    }
    __syncthreads();
    float4 sc = shsc[cl], sf = shsf[cl];
    __half2* op = (__half2*)out + (size_t)b * NPX * 32;
    for (int i = 0; i < PPG; i++) {
        int px = gg * PPG + i;
        float4 a = ip[(size_t)px * 16 + c4];
        float rx = fmaxf(a.x * sc.x + sf.x, 0.f);
        float ry = fmaxf(a.y * sc.y + sf.y, 0.f);
        float rz = fmaxf(a.z * sc.z + sf.z, 0.f);
        float rw = fmaxf(a.w * sc.w + sf.w, 0.f);
        op[(size_t)px * 32 + c4 * 2 + 0] = __floats2half2_rn(rx, ry);
        op[(size_t)px * 32 + c4 * 2 + 1] = __floats2half2_rn(rz, rw);
    }
}

// ---------------- head linear ------------------------------------------------
__global__ __launch_bounds__(256)
void linear_k(const float* __restrict__ pool, const float* __restrict__ W,
              const float* __restrict__ bias, float* __restrict__ out) {
    int idx = blockIdx.x * 256 + threadIdx.x;
    if (idx >= BB * 10) return;
    int b = idx / 10, n = idx % 10;
    float acc = bias[n];
#pragma unroll 8
    for (int c = 0; c < CC; c++) acc += pool[b * CC + c] * W[n * CC + c];
    out[idx] = acc;
}

// ---------------- launch -----------------------------------------------------
extern "C" void kernel_launch(void* const* d_in, const int* in_sizes, int n_in,
                              void* d_out, int out_size) {
    const float* x      = (const float*)d_in[0];
    const float* ds_w1  = (const float*)d_in[1];
    const float* ds_b1  = (const float*)d_in[2];
    const float* ds_n1w = (const float*)d_in[3];
    const float* ds_n1b = (const float*)d_in[4];
    const float* ds_w2  = (const float*)d_in[5];
    const float* ds_b2  = (const float*)d_in[6];
    const float* ds_n2w = (const float*)d_in[7];
    const float* ds_n2b = (const float*)d_in[8];
    const float* ds_w3  = (const float*)d_in[9];
    const float* ds_b3  = (const float*)d_in[10];
    const float* ode_w1 = (const float*)d_in[11];
    const float* ode_b1 = (const float*)d_in[12];
    const float* ode_n1w= (const float*)d_in[13];
    const float* ode_n1b= (const float*)d_in[14];
    const float* ode_w2 = (const float*)d_in[15];
    const float* ode_b2 = (const float*)d_in[16];
    const float* ode_n2w= (const float*)d_in[17];
    const float* ode_n2b= (const float*)d_in[18];
    const float* head_nw= (const float*)d_in[19];
    const float* head_nb= (const float*)d_in[20];
    const float* head_W = (const float*)d_in[21];
    const float* head_b = (const float*)d_in[22];
    float* out = (float*)d_out;

    float *h1, *h2, *z, *ka, *pool, *wcls;
    __half *h1h, *h2h, *zh, *u, *ga, *g, *bpk, *b4;
    cudaGetSymbolAddress((void**)&h1,  g_h1);
    cudaGetSymbolAddress((void**)&h1h, g_h1h);
    cudaGetSymbolAddress((void**)&h2,  g_h2);
    cudaGetSymbolAddress((void**)&h2h, g_h2h);
    cudaGetSymbolAddress((void**)&z,   g_z);
    cudaGetSymbolAddress((void**)&zh,  g_zh);
    cudaGetSymbolAddress((void**)&u,   g_u);
    cudaGetSymbolAddress((void**)&ga,  g_ga);
    cudaGetSymbolAddress((void**)&ka,  g_ka);
    cudaGetSymbolAddress((void**)&pool,g_pool);
    cudaGetSymbolAddress((void**)&g,   g_g);
    cudaGetSymbolAddress((void**)&bpk, g_BpackH);
    cudaGetSymbolAddress((void**)&b4,  g_B4);
    cudaGetSymbolAddress((void**)&wcls,g_Wcls);

    static int smem_set = 0;
    if (!smem_set) {
        cudaFuncSetAttribute(conv4_mma<128, 64>,
                             cudaFuncAttributeMaxDynamicSharedMemorySize, 6 * 128 * 36 * 2);
        cudaFuncSetAttribute(conv4_mma<64, 32>,
                             cudaFuncAttributeMaxDynamicSharedMemorySize, 10 * 64 * 36 * 2);
        smem_set = 1;
    }

    prep_w<<<512, 256>>>(ode_w1, ode_w2, ds_w2, ds_w3);

    // ---- downsampler ----
    conv1_k<<<dim3(256, 64), 256>>>(x, ds_w1, ds_b1, h1);
    gn_ds<16384><<<dim3(64, 4), 256>>>(h1, ds_n1w, ds_n1b, h1h);
    conv4_mma<128, 64><<<dim3(32, 64), 128, 6 * 128 * 36 * 2>>>(h1h, b4, ds_b2, h2, nullptr);
    gn_ds<4096><<<dim3(64, 4), 256>>>(h2, ds_n2w, ds_n2b, h2h);
    conv4_mma<64, 32><<<dim3(8, 64), 128, 10 * 64 * 36 * 2>>>(h2h, b4 + 32 * 2048, ds_b3, z, zh);

    // ---- ODE: 10 RK4 steps (R14 structure; k1 GN reads fp16 zh) ----
    dim3 cg(8, 64), gg(64, 4);
    const __half* w1p = bpk;
    const __half* w2p = bpk + 18 * 2048;
    const float* wc1 = wcls;
    const float* wc2 = wcls + 9 * 64;
    for (int i = 0; i < 10; i++) {
        float t = (float)i * 0.1f;
        // k1
        gn_sph<<<gg, 256>>>(zh, ode_n1w, ode_n1b, g);
        ode_conv_mma<0><<<cg, 128>>>(g, w1p, t,        ode_b1, wc1, u,  ka, z, zh);
        gn_sph<<<gg, 256>>>(u,  ode_n2w, ode_n2b, g);
        ode_conv_mma<1><<<cg, 128>>>(g, w2p, t,        ode_b2, wc2, ga, ka, z, zh);
        // k2
        gn_sph<<<gg, 256>>>(ga, ode_n1w, ode_n1b, g);
        ode_conv_mma<0><<<cg, 128>>>(g, w1p, t + .05f, ode_b1, wc1, u,  ka, z, zh);
        gn_sph<<<gg, 256>>>(u,  ode_n2w, ode_n2b, g);
        ode_conv_mma<2><<<cg, 128>>>(g, w2p, t + .05f, ode_b2, wc2, ga, ka, z, zh);
        // k3
        gn_sph<<<gg, 256>>>(ga, ode_n1w, ode_n1b, g);
        ode_conv_mma<0><<<cg, 128>>>(g, w1p, t + .05f, ode_b1, wc1, u,  ka, z, zh);
        gn_sph<<<gg, 256>>>(u,  ode_n2w, ode_n2b, g);
        ode_conv_mma<3><<<cg, 128>>>(g, w2p, t + .05f, ode_b2, wc2, ga, ka, z, zh);
        // k4
        gn_sph<<<gg, 256>>>(ga, ode_n1w, ode_n1b, g);
        ode_conv_mma<0><<<cg, 128>>>(g, w1p, t + .1f,  ode_b1, wc1, u,  ka, z, zh);
        gn_sph<<<gg, 256>>>(u,  ode_n2w, ode_n2b, g);
        ode_conv_mma<4><<<cg, 128>>>(g, w2p, t + .1f,  ode_b2, wc2, ga, ka, z, zh);
    }

    // ---- head ----
    gn_pool<<<gg, 256>>>(z, head_nw, head_nb, pool);
    linear_k<<<(BB * 10 + 255) / 256, 256>>>(pool, head_W, head_b, out);
}

// round 17
// speedup vs baseline: 1.1955x; 1.0300x over previous
#include <cuda_runtime.h>
#include <cuda_fp16.h>
#include <cstdint>

#define BB 64
#define CC 64
#define DT6 (0.1f/6.0f)

// ---------------- scratch (device globals) ---------------------------------
static __device__ __half g_h1h[BB*128*128*64];   // fp16 NHWC (conv1 out)
static __device__ float  g_h2 [BB*64*64*64];     // fp32 NHWC
static __device__ __half g_h2h[BB*64*64*64];     // fp16 NHWC
static __device__ float  g_z  [BB*1024*64];      // fp32 NHWC (ODE state)
static __device__ __half g_u  [BB*1024*64];      // fp16: convA output (GN2 in)
static __device__ __half g_ga [BB*1024*64];      // fp16: z+alpha*k (GN1 in)
static __device__ __half g_ka [BB*1024*64];      // fp16 RK4 accumulator
static __device__ __half g_g  [BB*1024*64];      // fp16 NHWC conv input
static __device__ float  g_pool[BB*CC];
// packed B: [chunk][nt][gid][tig][4 b32]
static __device__ __half g_BpackH[36*2048];      // ODE weights
static __device__ __half g_B4[2*32*2048];        // conv4 weights
static __device__ float  g_Wcls[2*3*3*64];       // time-channel border sums

// ---------------- fp16 MMA -------------------------------------------------
__device__ __forceinline__ void mma_f16(float* c, uint32_t a0, uint32_t a1,
                                        uint32_t a2, uint32_t a3,
                                        uint32_t b0, uint32_t b1) {
    asm volatile(
        "mma.sync.aligned.m16n8k16.row.col.f32.f16.f16.f32 "
        "{%0,%1,%2,%3},{%4,%5,%6,%7},{%8,%9},{%0,%1,%2,%3};"
        : "+f"(c[0]), "+f"(c[1]), "+f"(c[2]), "+f"(c[3])
        : "r"(a0), "r"(a1), "r"(a2), "r"(a3), "r"(b0), "r"(b1));
}

// ---------------- weight prepack -------------------------------------------
__global__ __launch_bounds__(256)
void prep_w(const float* __restrict__ w1, const float* __restrict__ w2,
            const float* __restrict__ w4a, const float* __restrict__ w4b) {
    int i = blockIdx.x * 256 + threadIdx.x;
    if (i < 36 * 2048) {                    // ODE conv weights
        int e = i & 1, w4 = (i >> 1) & 3, tig = (i >> 3) & 3;
        int gid = (i >> 5) & 7, nt = (i >> 8) & 7;
        int c = i >> 11;                    // cv*18 + s9*2 + h
        int h = c & 1, s9 = (c >> 1) % 9, cv = c / 18;
        int dy = s9 / 3, dx = s9 % 3;
        int kk = w4 >> 1, bsel = w4 & 1;
        int k = kk * 16 + 2 * tig + bsel * 8 + e;
        int oc = nt * 8 + gid;
        const float* w = cv ? w2 : w1;
        int icg = h * 32 + k;
        g_BpackH[i] = __float2half(w[((oc * 65 + icg + 1) * 3 + dy) * 3 + dx]);
    }
    if (i < 2 * 32 * 2048) {                // conv4 weights
        int e = i & 1, w4 = (i >> 1) & 3, tig = (i >> 3) & 3;
        int gid = (i >> 5) & 7, nt = (i >> 8) & 7;
        int tix = (i >> 11) & 31;           // tap*2 + h
        int cv = i >> 16;
        int h = tix & 1, tap = tix >> 1;
        int ky = tap >> 2, kx = tap & 3;
        int kk = w4 >> 1, bsel = w4 & 1;
        int k = kk * 16 + 2 * tig + bsel * 8 + e;
        int oc = nt * 8 + gid;
        const float* w = cv ? w4b : w4a;
        int ic = h * 32 + k;
        g_B4[i] = __float2half(w[((oc * 64 + ic) * 4 + ky) * 4 + kx]);
    }
    if (i < 2 * 3 * 3 * 64) {               // time-channel border-class sums
        int oc = i & 63;
        int t2 = i >> 6;
        int xs = t2 % 3, ys = (t2 / 3) % 3, cv = t2 / 9;
        const float* w = cv ? w2 : w1;
        float s = 0.f;
        for (int dy = 0; dy < 3; dy++)
            for (int dx = 0; dx < 3; dx++) {
                bool okY = !((ys == 0 && dy == 0) || (ys == 2 && dy == 2));
                bool okX = !((xs == 0 && dx == 0) || (xs == 2 && dx == 2));
                if (okY && okX) s += w[(oc * 65 * 3 + dy) * 3 + dx];
            }
        g_Wcls[((cv * 3 + ys) * 3 + xs) * 64 + oc] = s;
    }
}

// ---------------- HMMA ODE conv 3x3 pad1 (smem A, fp16 outb, fp16 ka) -------
// MODE 0 (convA): outb = fp16(v)
// MODE 1 (k1):    ka = fp16(v);    outb = fp16(z + 0.05v)
// MODE 2 (k2):    ka += 2v (fp16); outb = fp16(z + 0.05v)
// MODE 3 (k3):    ka += 2v (fp16); outb = fp16(z + 0.10v)
// MODE 4 (k4):    z += DT6*(ka+v)
template <int MODE>
__global__ __launch_bounds__(128)
void ode_conv_mma(const __half* __restrict__ g, const __half* __restrict__ wpk,
                  float t, const float* __restrict__ bias,
                  const float* __restrict__ wcls,
                  __half* __restrict__ outb, __half* __restrict__ ka,
                  float* __restrict__ z) {
    __shared__ __half sA[192 * 72];          // 6 rows x 32 x, stride 72 halves
    int q = blockIdx.x, b = blockIdx.y;
    int tid = threadIdx.x;
    int w = tid >> 5, lane = tid & 31;
    int gid = lane >> 2, tig = lane & 3;
    int y = 4 * q + w;

    const __half* gb = g + (size_t)b * 65536;
#pragma unroll
    for (int j = 0; j < 12; j++) {
        int s = tid + 128 * j;
        int px = s >> 3, c8 = s & 7;
        int x = px & 31, yy = px >> 5;
        int yg = 4 * q - 1 + yy;
        uint4 v = make_uint4(0u, 0u, 0u, 0u);
        if (yg >= 0 && yg < 32)
            v = *(const uint4*)(gb + ((size_t)yg * 32 + x) * 64 + c8 * 8);
        *(uint4*)(&sA[px * 72 + c8 * 8]) = v;
    }
    __syncthreads();

    float acc[2][8][4];
#pragma unroll
    for (int mt = 0; mt < 2; mt++)
#pragma unroll
        for (int nt = 0; nt < 8; nt++)
#pragma unroll
            for (int j = 0; j < 4; j++) acc[mt][nt][j] = 0.f;

#pragma unroll
    for (int c = 0; c < 18; c++) {
        int s9 = c >> 1, h = c & 1;
        int dy = s9 / 3, dx = s9 % 3;
        int yyl = w + dy;

        int xA0 = gid + dx - 1;
        int xA1 = xA0 + 8, xA2 = xA0 + 16, xA3 = xA0 + 24;
        bool ok0 = (xA0 >= 0) && (xA0 < 32);
        bool ok1 = (xA1 >= 0) && (xA1 < 32);
        bool ok2 = (xA2 >= 0) && (xA2 < 32);
        bool ok3 = (xA3 >= 0) && (xA3 < 32);
        int r0 = (yyl * 32 + xA0) * 72 + h * 32;
        int r1 = (yyl * 32 + xA1) * 72 + h * 32;
        int r2 = (yyl * 32 + xA2) * 72 + h * 32;
        int r3 = (yyl * 32 + xA3) * 72 + h * 32;

        uint32_t A[2][2][4];
#pragma unroll
        for (int kk = 0; kk < 2; kk++) {
            int ic = kk * 16 + 2 * tig;
            A[kk][0][0] = ok0 ? *(const uint32_t*)(&sA[r0 + ic]) : 0u;
            A[kk][0][1] = ok1 ? *(const uint32_t*)(&sA[r1 + ic]) : 0u;
            A[kk][0][2] = ok0 ? *(const uint32_t*)(&sA[r0 + ic + 8]) : 0u;
            A[kk][0][3] = ok1 ? *(const uint32_t*)(&sA[r1 + ic + 8]) : 0u;
            A[kk][1][0] = ok2 ? *(const uint32_t*)(&sA[r2 + ic]) : 0u;
            A[kk][1][1] = ok3 ? *(const uint32_t*)(&sA[r3 + ic]) : 0u;
            A[kk][1][2] = ok2 ? *(const uint32_t*)(&sA[r2 + ic + 8]) : 0u;
            A[kk][1][3] = ok3 ? *(const uint32_t*)(&sA[r3 + ic + 8]) : 0u;
        }

        const uint4* wp4 = (const uint4*)(wpk + (size_t)c * 2048);
#pragma unroll
        for (int nt = 0; nt < 8; nt++) {
            uint4 wv = __ldg(wp4 + (nt * 8 + gid) * 4 + tig);
            mma_f16(acc[0][nt], A[0][0][0], A[0][0][1], A[0][0][2], A[0][0][3], wv.x, wv.y);
            mma_f16(acc[1][nt], A[0][1][0], A[0][1][1], A[0][1][2], A[0][1][3], wv.x, wv.y);
            mma_f16(acc[0][nt], A[1][0][0], A[1][0][1], A[1][0][2], A[1][0][3], wv.z, wv.w);
            mma_f16(acc[1][nt], A[1][1][0], A[1][1][1], A[1][1][2], A[1][1][3], wv.z, wv.w);
        }
    }

    int ys = (y == 0) ? 0 : ((y == 31) ? 2 : 1);
    const float* wcy = wcls + ys * 3 * 64;
#pragma unroll
    for (int mt = 0; mt < 2; mt++) {
#pragma unroll
        for (int rr = 0; rr < 2; rr++) {
            int x = mt * 16 + gid + rr * 8;
            int xs = (x == 0) ? 0 : ((x == 31) ? 2 : 1);
            const float* wcx = wcy + xs * 64;
            size_t base = ((size_t)b * 1024 + y * 32 + x) * 64;
#pragma unroll
            for (int nt = 0; nt < 8; nt++) {
                int oc = nt * 8 + 2 * tig;
                float2 v;
                v.x = acc[mt][nt][rr * 2 + 0] + __ldg(bias + oc) + t * __ldg(wcx + oc);
                v.y = acc[mt][nt][rr * 2 + 1] + __ldg(bias + oc + 1) + t * __ldg(wcx + oc + 1);
                if (MODE == 0) {
                    *(__half2*)(outb + base + oc) = __floats2half2_rn(v.x, v.y);
                } else if (MODE == 1) {
                    *(__half2*)(ka + base + oc) = __floats2half2_rn(v.x, v.y);
                    float2 zz = *(const float2*)(z + base + oc);
                    *(__half2*)(outb + base + oc) =
                        __floats2half2_rn(zz.x + 0.05f * v.x, zz.y + 0.05f * v.y);
                } else if (MODE == 2 || MODE == 3) {
                    float2 a = __half22float2(*(__half2*)(ka + base + oc));
                    a.x += 2.f * v.x; a.y += 2.f * v.y;
                    *(__half2*)(ka + base + oc) = __floats2half2_rn(a.x, a.y);
                    const float alpha = (MODE == 2) ? 0.05f : 0.1f;
                    float2 zz = *(const float2*)(z + base + oc);
                    *(__half2*)(outb + base + oc) =
                        __floats2half2_rn(zz.x + alpha * v.x, zz.y + alpha * v.y);
                } else {
                    float2 a = __half22float2(*(__half2*)(ka + base + oc));
                    float2 zz = *(const float2*)(z + base + oc);
                    zz.x += DT6 * (a.x + v.x);
                    zz.y += DT6 * (a.y + v.y);
                    *(float2*)(z + base + oc) = zz;
                }
            }
        }
    }
}

// ---------------- single-pass GN + ReLU, fp32 in -> fp16 (k1 only) ----------
__global__ __launch_bounds__(256)
void gn_spf(const float* __restrict__ in, const float* __restrict__ gw,
            const float* __restrict__ gb, __half* __restrict__ out) {
    int b = blockIdx.x, qtr = blockIdx.y;
    int tid = threadIdx.x;
    int cl = tid & 3, c4 = qtr * 4 + cl, gg = tid >> 2;
    const float4* ip = (const float4*)in + (size_t)b * 16384;

    float4 v[16];
    float4 s = {0, 0, 0, 0}, q2 = {0, 0, 0, 0};
#pragma unroll
    for (int i = 0; i < 16; i++) {
        v[i] = ip[(gg * 16 + i) * 16 + c4];
        s.x += v[i].x; s.y += v[i].y; s.z += v[i].z; s.w += v[i].w;
        q2.x += v[i].x * v[i].x; q2.y += v[i].y * v[i].y;
        q2.z += v[i].z * v[i].z; q2.w += v[i].w * v[i].w;
    }
    __shared__ float4 shs[64][4], shq[64][4];
    __shared__ float4 shsc[4], shsf[4];
    shs[gg][cl] = s; shq[gg][cl] = q2;
    __syncthreads();
    if (tid < 4) {
        float4 S = {0, 0, 0, 0}, Q = {0, 0, 0, 0};
        for (int g2 = 0; g2 < 64; g2++) {
            float4 a = shs[g2][tid], c = shq[g2][tid];
            S.x += a.x; S.y += a.y; S.z += a.z; S.w += a.w;
            Q.x += c.x; Q.y += c.y; Q.z += c.z; Q.w += c.w;
        }
        float4 gw4 = ((const float4*)gw)[qtr * 4 + tid];
        float4 gb4 = ((const float4*)gb)[qtr * 4 + tid];
        float4 sc, sf;
        float m, var;
        m = S.x / 1024.f; var = Q.x / 1024.f - m * m; sc.x = gw4.x * rsqrtf(var + 1e-5f); sf.x = gb4.x - m * sc.x;
        m = S.y / 1024.f; var = Q.y / 1024.f - m * m; sc.y = gw4.y * rsqrtf(var + 1e-5f); sf.y = gb4.y - m * sc.y;
        m = S.z / 1024.f; var = Q.z / 1024.f - m * m; sc.z = gw4.z * rsqrtf(var + 1e-5f); sf.z = gb4.z - m * sc.z;
        m = S.w / 1024.f; var = Q.w / 1024.f - m * m; sc.w = gw4.w * rsqrtf(var + 1e-5f); sf.w = gb4.w - m * sc.w;
        shsc[tid] = sc; shsf[tid] = sf;
    }
    __syncthreads();
    float4 sc = shsc[cl], sf = shsf[cl];
    __half2* op = (__half2*)out + (size_t)b * 32768;
#pragma unroll
    for (int i = 0; i < 16; i++) {
        int px = gg * 16 + i;
        float rx = fmaxf(fmaf(v[i].x, sc.x, sf.x), 0.f);
        float ry = fmaxf(fmaf(v[i].y, sc.y, sf.y), 0.f);
        float rz = fmaxf(fmaf(v[i].z, sc.z, sf.z), 0.f);
        float rw = fmaxf(fmaf(v[i].w, sc.w, sf.w), 0.f);
        op[px * 32 + c4 * 2 + 0] = __floats2half2_rn(rx, ry);
        op[px * 32 + c4 * 2 + 1] = __floats2half2_rn(rz, rw);
    }
}

// ---------------- single-pass GN + ReLU, fp16 in -> fp16 --------------------
__global__ __launch_bounds__(256)
void gn_sph(const __half* __restrict__ in, const float* __restrict__ gw,
            const float* __restrict__ gb, __half* __restrict__ out) {
    int b = blockIdx.x, qtr = blockIdx.y;
    int tid = threadIdx.x;
    int cl = tid & 3, c4 = qtr * 4 + cl, gg = tid >> 2;
    const uint2* ip = (const uint2*)in + (size_t)b * 16384;

    uint2 raw[16];
    float4 s = {0, 0, 0, 0}, q2 = {0, 0, 0, 0};
#pragma unroll
    for (int i = 0; i < 16; i++) {
        raw[i] = ip[(gg * 16 + i) * 16 + c4];
        float2 fa = __half22float2(*(__half2*)&raw[i].x);
        float2 fb = __half22float2(*(__half2*)&raw[i].y);
        s.x += fa.x; s.y += fa.y; s.z += fb.x; s.w += fb.y;
        q2.x += fa.x * fa.x; q2.y += fa.y * fa.y;
        q2.z += fb.x * fb.x; q2.w += fb.y * fb.y;
    }
    __shared__ float4 shs[64][4], shq[64][4];
    __shared__ float4 shsc[4], shsf[4];
    shs[gg][cl] = s; shq[gg][cl] = q2;
    __syncthreads();
    if (tid < 4) {
        float4 S = {0, 0, 0, 0}, Q = {0, 0, 0, 0};
        for (int g2 = 0; g2 < 64; g2++) {
            float4 a = shs[g2][tid], c = shq[g2][tid];
            S.x += a.x; S.y += a.y; S.z += a.z; S.w += a.w;
            Q.x += c.x; Q.y += c.y; Q.z += c.z; Q.w += c.w;
        }
        float4 gw4 = ((const float4*)gw)[qtr * 4 + tid];
        float4 gb4 = ((const float4*)gb)[qtr * 4 + tid];
        float4 sc, sf;
        float m, var;
        m = S.x / 1024.f; var = Q.x / 1024.f - m * m; sc.x = gw4.x * rsqrtf(var + 1e-5f); sf.x = gb4.x - m * sc.x;
        m = S.y / 1024.f; var = Q.y / 1024.f - m * m; sc.y = gw4.y * rsqrtf(var + 1e-5f); sf.y = gb4.y - m * sc.y;
        m = S.z / 1024.f; var = Q.z / 1024.f - m * m; sc.z = gw4.z * rsqrtf(var + 1e-5f); sf.z = gb4.z - m * sc.z;
        m = S.w / 1024.f; var = Q.w / 1024.f - m * m; sc.w = gw4.w * rsqrtf(var + 1e-5f); sf.w = gb4.w - m * sc.w;
        shsc[tid] = sc; shsf[tid] = sf;
    }
    __syncthreads();
    float4 sc = shsc[cl], sf = shsf[cl];
    __half2* op = (__half2*)out + (size_t)b * 32768;
#pragma unroll
    for (int i = 0; i < 16; i++) {
        int px = gg * 16 + i;
        float2 fa = __half22float2(*(__half2*)&raw[i].x);
        float2 fb = __half22float2(*(__half2*)&raw[i].y);
        float rx = fmaxf(fmaf(fa.x, sc.x, sf.x), 0.f);
        float ry = fmaxf(fmaf(fa.y, sc.y, sf.y), 0.f);
        float rz = fmaxf(fmaf(fb.x, sc.z, sf.z), 0.f);
        float rw = fmaxf(fmaf(fb.y, sc.w, sf.w), 0.f);
        op[px * 32 + c4 * 2 + 0] = __floats2half2_rn(rx, ry);
        op[px * 32 + c4 * 2 + 1] = __floats2half2_rn(rz, rw);
    }
}

// ---------------- GN + ReLU + pool (head only, fp32 z) ----------------------
__global__ __launch_bounds__(256)
void gn_pool(const float* __restrict__ in, const float* __restrict__ gw,
             const float* __restrict__ gb, float* __restrict__ pool) {
    int b = blockIdx.x, qtr = blockIdx.y;
    int tid = threadIdx.x;
    int cl = tid & 3, c4 = qtr * 4 + cl, gg = tid >> 2;
    const float4* ip = (const float4*)in + (size_t)b * 16384;
    float4 s = {0, 0, 0, 0}, q2 = {0, 0, 0, 0};
#pragma unroll 4
    for (int i = 0; i < 16; i++) {
        float4 a = ip[(gg * 16 + i) * 16 + c4];
        s.x += a.x; s.y += a.y; s.z += a.z; s.w += a.w;
        q2.x += a.x * a.x; q2.y += a.y * a.y; q2.z += a.z * a.z; q2.w += a.w * a.w;
    }
    __shared__ float4 shs[64][4], shq[64][4];
    __shared__ float4 shsc[4], shsf[4];
    shs[gg][cl] = s; shq[gg][cl] = q2;
    __syncthreads();
    if (tid < 4) {
        float4 S = {0, 0, 0, 0}, Q = {0, 0, 0, 0};
        for (int g2 = 0; g2 < 64; g2++) {
            float4 a = shs[g2][tid], c = shq[g2][tid];
            S.x += a.x; S.y += a.y; S.z += a.z; S.w += a.w;
            Q.x += c.x; Q.y += c.y; Q.z += c.z; Q.w += c.w;
        }
        float4 gw4 = ((const float4*)gw)[qtr * 4 + tid];
        float4 gb4 = ((const float4*)gb)[qtr * 4 + tid];
        float4 sc, sf; float m, var;
        m = S.x / 1024.f; var = Q.x / 1024.f - m * m; sc.x = gw4.x * rsqrtf(var + 1e-5f); sf.x = gb4.x - m * sc.x;
        m = S.y / 1024.f; var = Q.y / 1024.f - m * m; sc.y = gw4.y * rsqrtf(var + 1e-5f); sf.y = gb4.y - m * sc.y;
        m = S.z / 1024.f; var = Q.z / 1024.f - m * m; sc.z = gw4.z * rsqrtf(var + 1e-5f); sf.z = gb4.z - m * sc.z;
        m = S.w / 1024.f; var = Q.w / 1024.f - m * m; sc.w = gw4.w * rsqrtf(var + 1e-5f); sf.w = gb4.w - m * sc.w;
        shsc[tid] = sc; shsf[tid] = sf;
    }
    __syncthreads();
    float4 sc = shsc[cl], sf = shsf[cl];
    float4 accp = {0, 0, 0, 0};
#pragma unroll 4
    for (int i = 0; i < 16; i++) {
        float4 a = ip[(gg * 16 + i) * 16 + c4];
        accp.x += fmaxf(a.x * sc.x + sf.x, 0.f);
        accp.y += fmaxf(a.y * sc.y + sf.y, 0.f);
        accp.z += fmaxf(a.z * sc.z + sf.z, 0.f);
        accp.w += fmaxf(a.w * sc.w + sf.w, 0.f);
    }
    __syncthreads();
    shs[gg][cl] = accp;
    __syncthreads();
    if (tid < 4) {
        float4 S = {0, 0, 0, 0};
        for (int g2 = 0; g2 < 64; g2++) {
            float4 a = shs[g2][tid];
            S.x += a.x; S.y += a.y; S.z += a.z; S.w += a.w;
        }
        int c0 = (qtr * 4 + tid) * 4;
        pool[b * CC + c0 + 0] = S.x / 1024.f;
        pool[b * CC + c0 + 1] = S.y / 1024.f;
        pool[b * CC + c0 + 2] = S.z / 1024.f;
        pool[b * CC + c0 + 3] = S.w / 1024.f;
    }
}

// ---------------- HMMA conv 4x4 stride2 pad1 (smem-staged A, h-phased) ------
template <int IH, int OH>
__global__ __launch_bounds__(128)
void conv4_mma(const __half* __restrict__ in, const __half* __restrict__ wpk,
               const float* __restrict__ bias, float* __restrict__ outF) {
    constexpr int IW = IH, OW = OH;
    constexpr int ROWS = (OH == 64) ? 6 : 10;
    extern __shared__ __half sA[];
    int q = blockIdx.x, b = blockIdx.y;
    int tid = threadIdx.x;
    int w = tid >> 5, lane = tid & 31;
    int gid = lane >> 2, tig = lane & 3;
    int oy, ox0, rbase;
    if (OH == 64) { oy = 2 * q + (w >> 1); ox0 = (w & 1) * 32; rbase = 4 * q - 1; }
    else          { oy = 4 * q + w;        ox0 = 0;            rbase = 8 * q - 1; }

    float acc[2][8][4];
#pragma unroll
    for (int mt = 0; mt < 2; mt++)
#pragma unroll
        for (int nt = 0; nt < 8; nt++)
#pragma unroll
            for (int j = 0; j < 4; j++) acc[mt][nt][j] = 0.f;

    const __half* inb = in + (size_t)b * IH * IW * 64;

#pragma unroll
    for (int h = 0; h < 2; h++) {
        if (h) __syncthreads();
        constexpr int NU2 = ROWS * IW * 8;
#pragma unroll 4
        for (int j = 0; j < NU2 / 128; j++) {
            int s = tid + 128 * j;
            int pxl = s >> 3, u2 = s & 7;
            int r = pxl / IW, x = pxl % IW;
            int iny = rbase + r;
            uint2 val = make_uint2(0u, 0u);
            if (iny >= 0 && iny < IH)
                val = *(const uint2*)(inb + ((size_t)iny * IW + x) * 64 + h * 32 + u2 * 4);
            *(uint2*)(&sA[pxl * 36 + u2 * 4]) = val;
        }
        __syncthreads();

#pragma unroll 2
        for (int tap = 0; tap < 16; tap++) {
            int dy = tap >> 2, dx = tap & 3;
            int rl = ((OH == 64) ? 2 * (w >> 1) : 2 * w) + dy;
            int xA[4]; bool ok[4];
#pragma unroll
            for (int u = 0; u < 4; u++) {
                int xi = (u >> 1) * 16 + (u & 1) * 8 + gid;
                int ix = 2 * (ox0 + xi) + dx - 1;
                xA[u] = ix;
                ok[u] = (ix >= 0) && (ix < IW);
            }
            uint32_t A[2][2][4];
#pragma unroll
            for (int kk = 0; kk < 2; kk++) {
                int ic = kk * 16 + 2 * tig;
                int a0 = (rl * IW + xA[0]) * 36 + ic;
                int a1 = (rl * IW + xA[1]) * 36 + ic;
                int a2 = (rl * IW + xA[2]) * 36 + ic;
                int a3 = (rl * IW + xA[3]) * 36 + ic;
                A[kk][0][0] = ok[0] ? *(const uint32_t*)(&sA[a0]) : 0u;
                A[kk][0][1] = ok[1] ? *(const uint32_t*)(&sA[a1]) : 0u;
                A[kk][0][2] = ok[0] ? *(const uint32_t*)(&sA[a0 + 8]) : 0u;
                A[kk][0][3] = ok[1] ? *(const uint32_t*)(&sA[a1 + 8]) : 0u;
                A[kk][1][0] = ok[2] ? *(const uint32_t*)(&sA[a2]) : 0u;
                A[kk][1][1] = ok[3] ? *(const uint32_t*)(&sA[a3]) : 0u;
                A[kk][1][2] = ok[2] ? *(const uint32_t*)(&sA[a2 + 8]) : 0u;
                A[kk][1][3] = ok[3] ? *(const uint32_t*)(&sA[a3 + 8]) : 0u;
            }
            const uint4* wp4 = (const uint4*)(wpk + (size_t)(tap * 2 + h) * 2048);
#pragma unroll
            for (int nt = 0; nt < 8; nt++) {
                uint4 wv = __ldg(wp4 + (nt * 8 + gid) * 4 + tig);
                mma_f16(acc[0][nt], A[0][0][0], A[0][0][1], A[0][0][2], A[0][0][3], wv.x, wv.y);
                mma_f16(acc[1][nt], A[0][1][0], A[0][1][1], A[0][1][2], A[0][1][3], wv.x, wv.y);
                mma_f16(acc[0][nt], A[1][0][0], A[1][0][1], A[1][0][2], A[1][0][3], wv.z, wv.w);
                mma_f16(acc[1][nt], A[1][1][0], A[1][1][1], A[1][1][2], A[1][1][3], wv.z, wv.w);
            }
        }
    }

#pragma unroll
    for (int mt = 0; mt < 2; mt++) {
#pragma unroll
        for (int rr = 0; rr < 2; rr++) {
            int x = ox0 + mt * 16 + gid + rr * 8;
            size_t base = ((size_t)(b * OH + oy) * OW + x) * 64;
#pragma unroll
            for (int nt = 0; nt < 8; nt++) {
                int oc = nt * 8 + 2 * tig;
                float2 v;
                v.x = acc[mt][nt][rr * 2 + 0] + __ldg(bias + oc);
                v.y = acc[mt][nt][rr * 2 + 1] + __ldg(bias + oc + 1);
                *(float2*)(outF + base + oc) = v;
            }
        }
    }
}

// ---------------- conv1: 1->64, 3x3 VALID, fp16 NHWC out --------------------
__global__ __launch_bounds__(256)
void conv1_k(const float* __restrict__ x, const float* __restrict__ w,
             const float* __restrict__ bias, __half* __restrict__ h1) {
    __shared__ float sIn[3 * 66];
    __shared__ float sW[576], sB[64];
    int slab = blockIdx.x, b = blockIdx.y;
    int row = slab >> 1, xbase = (slab & 1) * 64;
    int tid = threadIdx.x;
    for (int i = tid; i < 576; i += 256) sW[i] = w[i];
    if (tid < 64) sB[tid] = bias[tid];
    for (int i = tid; i < 198; i += 256) {
        int r = i / 66, c = i % 66;
        sIn[i] = x[((size_t)b * 130 + row + r) * 130 + xbase + c];
    }
    __syncthreads();
    int oc = tid & 63, pl = tid >> 6;
#pragma unroll 4
    for (int i = 0; i < 16; i++) {
        int lx = pl * 16 + i;
        float a = sB[oc];
#pragma unroll
        for (int ky = 0; ky < 3; ky++)
#pragma unroll
            for (int kx = 0; kx < 3; kx++)
                a = fmaf(sW[oc * 9 + ky * 3 + kx], sIn[ky * 66 + lx + kx], a);
        h1[((size_t)b * 16384 + row * 128 + xbase + lx) * 64 + oc] = __float2half(a);
    }
}

// ---------------- GN + ReLU NHWC fp16 -> fp16 (downsampler, 2-pass) ---------
template <int NPX>
__global__ __launch_bounds__(256)
void gn_dsh(const __half* __restrict__ in, const float* __restrict__ gw,
            const float* __restrict__ gb, __half* __restrict__ out) {
    constexpr int PPG = NPX / 64;
    int b = blockIdx.x, qtr = blockIdx.y;
    int tid = threadIdx.x;
    int cl = tid & 3, c4 = qtr * 4 + cl, gg = tid >> 2;
    const uint2* ip = (const uint2*)in + (size_t)b * NPX * 16;
    float4 s = {0, 0, 0, 0}, q2 = {0, 0, 0, 0};
    for (int i = 0; i < PPG; i++) {
        int px = gg * PPG + i;
        uint2 r = ip[(size_t)px * 16 + c4];
        float2 fa = __half22float2(*(__half2*)&r.x);
        float2 fb = __half22float2(*(__half2*)&r.y);
        s.x += fa.x; s.y += fa.y; s.z += fb.x; s.w += fb.y;
        q2.x += fa.x * fa.x; q2.y += fa.y * fa.y;
        q2.z += fb.x * fb.x; q2.w += fb.y * fb.y;
    }
    __shared__ float4 shs[64][4], shq[64][4];
    __shared__ float4 shsc[4], shsf[4];
    shs[gg][cl] = s; shq[gg][cl] = q2;
    __syncthreads();
    if (tid < 4) {
        float4 S = {0, 0, 0, 0}, Q = {0, 0, 0, 0};
        for (int g2 = 0; g2 < 64; g2++) {
            float4 a = shs[g2][tid], c = shq[g2][tid];
            S.x += a.x; S.y += a.y; S.z += a.z; S.w += a.w;
            Q.x += c.x; Q.y += c.y; Q.z += c.z; Q.w += c.w;
        }
        float4 gw4 = ((const float4*)gw)[qtr * 4 + tid];
        float4 gb4 = ((const float4*)gb)[qtr * 4 + tid];
        float4 sc, sf; float m, var; const float inv = 1.f / (float)NPX;
        m = S.x*inv; var = Q.x*inv - m*m; sc.x = gw4.x*rsqrtf(var+1e-5f); sf.x = gb4.x - m*sc.x;
        m = S.y*inv; var = Q.y*inv - m*m; sc.y = gw4.y*rsqrtf(var+1e-5f); sf.y = gb4.y - m*sc.y;
        m = S.z*inv; var = Q.z*inv - m*m; sc.z = gw4.z*rsqrtf(var+1e-5f); sf.z = gb4.z - m*sc.z;
        m = S.w*inv; var = Q.w*inv - m*m; sc.w = gw4.w*rsqrtf(var+1e-5f); sf.w = gb4.w - m*sc.w;
        shsc[tid] = sc; shsf[tid] = sf;
    }
    __syncthreads();
    float4 sc = shsc[cl], sf = shsf[cl];
    __half2* op = (__half2*)out + (size_t)b * NPX * 32;
    for (int i = 0; i < PPG; i++) {
        int px = gg * PPG + i;
        uint2 r = ip[(size_t)px * 16 + c4];
        float2 fa = __half22float2(*(__half2*)&r.x);
        float2 fb = __half22float2(*(__half2*)&r.y);
        float rx = fmaxf(fa.x * sc.x + sf.x, 0.f);
        float ry = fmaxf(fa.y * sc.y + sf.y, 0.f);
        float rz = fmaxf(fb.x * sc.z + sf.z, 0.f);
        float rw = fmaxf(fb.y * sc.w + sf.w, 0.f);
        op[(size_t)px * 32 + c4 * 2 + 0] = __floats2half2_rn(rx, ry);
        op[(size_t)px * 32 + c4 * 2 + 1] = __floats2half2_rn(rz, rw);
    }
}

// ---------------- GN + ReLU NHWC fp32 -> fp16 (h2, 2-pass) ------------------
template <int NPX>
__global__ __launch_bounds__(256)
void gn_ds(const float* __restrict__ in, const float* __restrict__ gw,
           const float* __restrict__ gb, __half* __restrict__ out) {
    constexpr int PPG = NPX / 64;
    int b = blockIdx.x, qtr = blockIdx.y;
    int tid = threadIdx.x;
    int cl = tid & 3, c4 = qtr * 4 + cl, gg = tid >> 2;
    const float4* ip = (const float4*)in + (size_t)b * NPX * 16;
    float4 s = {0, 0, 0, 0}, q2 = {0, 0, 0, 0};
    for (int i = 0; i < PPG; i++) {
        int px = gg * PPG + i;
        float4 a = ip[(size_t)px * 16 + c4];
        s.x += a.x; s.y += a.y; s.z += a.z; s.w += a.w;
        q2.x += a.x * a.x; q2.y += a.y * a.y; q2.z += a.z * a.z; q2.w += a.w * a.w;
    }
    __shared__ float4 shs[64][4], shq[64][4];
    __shared__ float4 shsc[4], shsf[4];
    shs[gg][cl] = s; shq[gg][cl] = q2;
    __syncthreads();
    if (tid < 4) {
        float4 S = {0, 0, 0, 0}, Q = {0, 0, 0, 0};
        for (int g2 = 0; g2 < 64; g2++) {
            float4 a = shs[g2][tid], c = shq[g2][tid];
            S.x += a.x; S.y += a.y; S.z += a.z; S.w += a.w;
            Q.x += c.x; Q.y += c.y; Q.z += c.z; Q.w += c.w;
        }
        float4 gw4 = ((const float4*)gw)[qtr * 4 + tid];
        float4 gb4 = ((const float4*)gb)[qtr * 4 + tid];
        float4 sc, sf; float m, var; const float inv = 1.f / (float)NPX;
        m = S.x*inv; var = Q.x*inv - m*m; sc.x = gw4.x*rsqrtf(var+1e-5f); sf.x = gb4.x - m*sc.x;
        m = S.y*inv; var = Q.y*inv - m*m; sc.y = gw4.y*rsqrtf(var+1e-5f); sf.y = gb4.y - m*sc.y;
        m = S.z*inv; var = Q.z*inv - m*m; sc.z = gw4.z*rsqrtf(var+1e-5f); sf.z = gb4.z - m*sc.z;
        m = S.w*inv; var = Q.w*inv - m*m; sc.w = gw4.w*rsqrtf(var+1e-5f); sf.w = gb4.w - m*sc.w;
        shsc[tid] = sc; shsf[tid] = sf;
    }
    __syncthreads();
    float4 sc = shsc[cl], sf = shsf[cl];
    __half2* op = (__half2*)out + (size_t)b * NPX * 32;
    for (int i = 0; i < PPG; i++) {
        int px = gg * PPG + i;
        float4 a = ip[(size_t)px * 16 + c4];
        float rx = fmaxf(a.x * sc.x + sf.x, 0.f);
        float ry = fmaxf(a.y * sc.y + sf.y, 0.f);
        float rz = fmaxf(a.z * sc.z + sf.z, 0.f);
        float rw = fmaxf(a.w * sc.w + sf.w, 0.f);
        op[(size_t)px * 32 + c4 * 2 + 0] = __floats2half2_rn(rx, ry);
        op[(size_t)px * 32 + c4 * 2 + 1] = __floats2half2_rn(rz, rw);
    }
}

// ---------------- head linear ------------------------------------------------
__global__ __launch_bounds__(256)
void linear_k(const float* __restrict__ pool, const float* __restrict__ W,
              const float* __restrict__ bias, float* __restrict__ out) {
    int idx = blockIdx.x * 256 + threadIdx.x;
    if (idx >= BB * 10) return;
    int b = idx / 10, n = idx % 10;
    float acc = bias[n];
#pragma unroll 8
    for (int c = 0; c < CC; c++) acc += pool[b * CC + c] * W[n * CC + c];
    out[idx] = acc;
}

// ---------------- launch -----------------------------------------------------
extern "C" void kernel_launch(void* const* d_in, const int* in_sizes, int n_in,
                              void* d_out, int out_size) {
    const float* x      = (const float*)d_in[0];
    const float* ds_w1  = (const float*)d_in[1];
    const float* ds_b1  = (const float*)d_in[2];
    const float* ds_n1w = (const float*)d_in[3];
    const float* ds_n1b = (const float*)d_in[4];
    const float* ds_w2  = (const float*)d_in[5];
    const float* ds_b2  = (const float*)d_in[6];
    const float* ds_n2w = (const float*)d_in[7];
    const float* ds_n2b = (const float*)d_in[8];
    const float* ds_w3  = (const float*)d_in[9];
    const float* ds_b3  = (const float*)d_in[10];
    const float* ode_w1 = (const float*)d_in[11];
    const float* ode_b1 = (const float*)d_in[12];
    const float* ode_n1w= (const float*)d_in[13];
    const float* ode_n1b= (const float*)d_in[14];
    const float* ode_w2 = (const float*)d_in[15];
    const float* ode_b2 = (const float*)d_in[16];
    const float* ode_n2w= (const float*)d_in[17];
    const float* ode_n2b= (const float*)d_in[18];
    const float* head_nw= (const float*)d_in[19];
    const float* head_nb= (const float*)d_in[20];
    const float* head_W = (const float*)d_in[21];
    const float* head_b = (const float*)d_in[22];
    float* out = (float*)d_out;

    float *h2, *z, *pool, *wcls;
    __half *h1h, *h2h, *u, *ga, *ka, *g, *bpk, *b4;
    cudaGetSymbolAddress((void**)&h1h, g_h1h);
    cudaGetSymbolAddress((void**)&h2,  g_h2);
    cudaGetSymbolAddress((void**)&h2h, g_h2h);
    cudaGetSymbolAddress((void**)&z,   g_z);
    cudaGetSymbolAddress((void**)&u,   g_u);
    cudaGetSymbolAddress((void**)&ga,  g_ga);
    cudaGetSymbolAddress((void**)&ka,  g_ka);
    cudaGetSymbolAddress((void**)&pool,g_pool);
    cudaGetSymbolAddress((void**)&g,   g_g);
    cudaGetSymbolAddress((void**)&bpk, g_BpackH);
    cudaGetSymbolAddress((void**)&b4,  g_B4);
    cudaGetSymbolAddress((void**)&wcls,g_Wcls);

    static int smem_set = 0;
    if (!smem_set) {
        cudaFuncSetAttribute(conv4_mma<128, 64>,
                             cudaFuncAttributeMaxDynamicSharedMemorySize, 6 * 128 * 36 * 2);
        cudaFuncSetAttribute(conv4_mma<64, 32>,
                             cudaFuncAttributeMaxDynamicSharedMemorySize, 10 * 64 * 36 * 2);
        smem_set = 1;
    }

    prep_w<<<512, 256>>>(ode_w1, ode_w2, ds_w2, ds_w3);

    // ---- downsampler ----
    conv1_k<<<dim3(256, 64), 256>>>(x, ds_w1, ds_b1, h1h);
    gn_dsh<16384><<<dim3(64, 4), 256>>>(h1h, ds_n1w, ds_n1b, h1h);
    conv4_mma<128, 64><<<dim3(32, 64), 128, 6 * 128 * 36 * 2>>>(h1h, b4, ds_b2, h2);
    gn_ds<4096><<<dim3(64, 4), 256>>>(h2, ds_n2w, ds_n2b, h2h);
    conv4_mma<64, 32><<<dim3(8, 64), 128, 10 * 64 * 36 * 2>>>(h2h, b4 + 32 * 2048, ds_b3, z);

    // ---- ODE: 10 RK4 steps ----
    dim3 cg(8, 64), gg(64, 4);
    const __half* w1p = bpk;
    const __half* w2p = bpk + 18 * 2048;
    const float* wc1 = wcls;
    const float* wc2 = wcls + 9 * 64;
    for (int i = 0; i < 10; i++) {
        float t = (float)i * 0.1f;
        // k1
        gn_spf<<<gg, 256>>>(z,  ode_n1w, ode_n1b, g);
        ode_conv_mma<0><<<cg, 128>>>(g, w1p, t,        ode_b1, wc1, u,  ka, z);
        gn_sph<<<gg, 256>>>(u,  ode_n2w, ode_n2b, g);
        ode_conv_mma<1><<<cg, 128>>>(g, w2p, t,        ode_b2, wc2, ga, ka, z);
        // k2
        gn_sph<<<gg, 256>>>(ga, ode_n1w, ode_n1b, g);
        ode_conv_mma<0><<<cg, 128>>>(g, w1p, t + .05f, ode_b1, wc1, u,  ka, z);
        gn_sph<<<gg, 256>>>(u,  ode_n2w, ode_n2b, g);
        ode_conv_mma<2><<<cg, 128>>>(g, w2p, t + .05f, ode_b2, wc2, ga, ka, z);
        // k3
        gn_sph<<<gg, 256>>>(ga, ode_n1w, ode_n1b, g);
        ode_conv_mma<0><<<cg, 128>>>(g, w1p, t + .05f, ode_b1, wc1, u,  ka, z);
        gn_sph<<<gg, 256>>>(u,  ode_n2w, ode_n2b, g);
        ode_conv_mma<3><<<cg, 128>>>(g, w2p, t + .05f, ode_b2, wc2, ga, ka, z);
        // k4
        gn_sph<<<gg, 256>>>(ga, ode_n1w, ode_n1b, g);
        ode_conv_mma<0><<<cg, 128>>>(g, w1p, t + .1f,  ode_b1, wc1, u,  ka, z);
        gn_sph<<<gg, 256>>>(u,  ode_n2w, ode_n2b, g);
        ode_conv_mma<4><<<cg, 128>>>(g, w2p, t + .1f,  ode_b2, wc2, ga, ka, z);
    }

    // ---- head ----
    gn_pool<<<gg, 256>>>(z, head_nw, head_nb, pool);
    linear_k<<<(BB * 10 + 255) / 256, 256>>>(pool, head_W, head_b, out);
}